// round 13
// baseline (speedup 1.0000x reference)
#include <cuda_runtime.h>
#include <cuda_fp16.h>
#include <cstdint>

// ---------------------------------------------------------------------------
// FragmentGraphEncoder: GNN forward
//   fp16 mma.sync (m16n8k16) conv GEMMs, BM=128 BN=128, 256 thr, ldmatrix
//   fragment loads, cp.async 5-stage pipeline, CSR aggregation, fp32 accum
// ---------------------------------------------------------------------------

#define H 512
#define INF 16
#define LAYERS 3
#define NMAX 50176
#define GMAX 512
#define EMAX 1048576

__device__ __half g_hA[(size_t)NMAX * H];
__device__ __half g_hB[(size_t)NMAX * H];
__device__ __half g_agg[(size_t)NMAX * H];
__device__ __half g_Wt[(size_t)LAYERS * 2 * H * H];   // fp16, [n][k]
__device__ float  g_pooled[GMAX * H];
__device__ float  g_counts[GMAX];
__device__ int    g_flags[2];
// CSR scratch
__device__ int    g_deg[NMAX];
__device__ int    g_rowptr[NMAX + 1];
__device__ int    g_cursor[NMAX];
__device__ int    g_csums[64];
__device__ int    g_col[EMAX];

// ---------------------------------------------------------------------------
__device__ __forceinline__ void red_add_v4(float* addr, float4 v) {
    asm volatile("red.global.add.v4.f32 [%0], {%1, %2, %3, %4};"
                 :: "l"(addr), "f"(v.x), "f"(v.y), "f"(v.z), "f"(v.w) : "memory");
}
__device__ __forceinline__ void mma_f16(float* c, const uint32_t* a, const uint32_t* b) {
    asm("mma.sync.aligned.m16n8k16.row.col.f32.f16.f16.f32 "
        "{%0,%1,%2,%3}, {%4,%5,%6,%7}, {%8,%9}, {%0,%1,%2,%3};"
        : "+f"(c[0]), "+f"(c[1]), "+f"(c[2]), "+f"(c[3])
        : "r"(a[0]), "r"(a[1]), "r"(a[2]), "r"(a[3]), "r"(b[0]), "r"(b[1]));
}
__device__ __forceinline__ void ldmatrix_x4(uint32_t& r0, uint32_t& r1,
                                            uint32_t& r2, uint32_t& r3, uint32_t addr) {
    asm volatile("ldmatrix.sync.aligned.m8n8.x4.shared.b16 {%0,%1,%2,%3}, [%4];"
                 : "=r"(r0), "=r"(r1), "=r"(r2), "=r"(r3) : "r"(addr));
}
__device__ __forceinline__ uint32_t smem_u32(const void* p) {
    uint32_t a;
    asm("{ .reg .u64 t; cvta.to.shared.u64 t, %1; cvt.u32.u64 %0, t; }" : "=r"(a) : "l"(p));
    return a;
}
__device__ __forceinline__ void cp_async16(uint32_t dst, const void* src) {
    asm volatile("cp.async.cg.shared.global [%0], [%1], 16;" :: "r"(dst), "l"(src));
}

// Detect int64 vs int32 index buffers
__global__ void detect_i64(const int* __restrict__ w, long n_words, int* flag) {
    long i = (long)blockIdx.x * blockDim.x + threadIdx.x;
    long idx = 2 * i + 1;
    if (idx < n_words && w[idx] != 0) *flag = 0;
}
__device__ __forceinline__ long ld_idx(const void* p, long i, int f64) {
    return f64 ? (long)((const long long*)p)[i] : (long)((const int*)p)[i];
}

// ---------------------------------------------------------------------------
// CSR build (graph is layer-invariant: build once per call)
__global__ void hist_dst(const void* __restrict__ ei, int E,
                         const int* __restrict__ flag, int* __restrict__ deg) {
    int f64 = flag[0];
    int e = blockIdx.x * blockDim.x + threadIdx.x;
    if (e >= E) return;
    int dst = (int)ld_idx(ei, (long)E + e, f64);
    atomicAdd(&deg[dst], 1);
}

__global__ void chunk_sums(const int* __restrict__ deg, int* __restrict__ sums, int N) {
    __shared__ int ws[8];
    int base = blockIdx.x << 10;
    int tid = threadIdx.x;            // 256
    int v = 0;
#pragma unroll
    for (int i = 0; i < 4; i++) {
        int idx = base + tid + i * 256;
        v += (idx < N) ? deg[idx] : 0;
    }
#pragma unroll
    for (int o = 16; o; o >>= 1) v += __shfl_xor_sync(~0u, v, o);
    if ((tid & 31) == 0) ws[tid >> 5] = v;
    __syncthreads();
    if (tid == 0) {
        int s = 0;
#pragma unroll
        for (int i = 0; i < 8; i++) s += ws[i];
        sums[blockIdx.x] = s;
    }
}

__global__ void scan_sums(int* __restrict__ sums, int* __restrict__ rowptr,
                          int nchunks, int N, int E) {
    int lane = threadIdx.x;
    int v0 = (lane < nchunks) ? sums[lane] : 0;
    int v1 = (lane + 32 < nchunks) ? sums[lane + 32] : 0;
    int x0 = v0;
#pragma unroll
    for (int o = 1; o < 32; o <<= 1) {
        int t = __shfl_up_sync(~0u, x0, o);
        if (lane >= o) x0 += t;
    }
    int tot0 = __shfl_sync(~0u, x0, 31);
    int x1 = v1;
#pragma unroll
    for (int o = 1; o < 32; o <<= 1) {
        int t = __shfl_up_sync(~0u, x1, o);
        if (lane >= o) x1 += t;
    }
    x1 += tot0;
    if (lane < nchunks) sums[lane] = x0 - v0;
    if (lane + 32 < nchunks) sums[lane + 32] = x1 - v1;
    if (lane == 0) rowptr[N] = E;
}

__global__ void scan_chunks(const int* __restrict__ deg, const int* __restrict__ csums,
                            int* __restrict__ rowptr, int* __restrict__ cursor, int N) {
    __shared__ int wsum[32];
    int base = blockIdx.x << 10;
    int tid = threadIdx.x, lane = tid & 31, w = tid >> 5;
    int i = base + tid;
    int v = (i < N) ? deg[i] : 0;
    int x = v;
#pragma unroll
    for (int o = 1; o < 32; o <<= 1) {
        int t = __shfl_up_sync(~0u, x, o);
        if (lane >= o) x += t;
    }
    if (lane == 31) wsum[w] = x;
    __syncthreads();
    if (w == 0) {
        int s = wsum[lane];
#pragma unroll
        for (int o = 1; o < 32; o <<= 1) {
            int t = __shfl_up_sync(~0u, s, o);
            if (lane >= o) s += t;
        }
        wsum[lane] = s;
    }
    __syncthreads();
    int excl = x - v + (w ? wsum[w - 1] : 0) + csums[blockIdx.x];
    if (i < N) { rowptr[i] = excl; cursor[i] = excl; }
}

__global__ void fill_csr(const void* __restrict__ ei, int E,
                         const int* __restrict__ flag,
                         int* __restrict__ cursor, int* __restrict__ col) {
    int f64 = flag[0];
    int e = blockIdx.x * blockDim.x + threadIdx.x;
    if (e >= E) return;
    int src = (int)ld_idx(ei, e, f64);
    int dst = (int)ld_idx(ei, (long)E + e, f64);
    int pos = atomicAdd(&cursor[dst], 1);
    col[pos] = src;
}

// ---------------------------------------------------------------------------
// agg[n] = fp16(sum_{j in row n} h[col[j]])  — fp32 accumulation
// 4 nodes per 256-thread block; 64 threads/node, one uint4 (8 halves) each
__global__ void gather_sum(const __half* __restrict__ h, const int* __restrict__ rowptr,
                           const int* __restrict__ col, __half* __restrict__ agg, int N) {
    int node = blockIdx.x * 4 + (threadIdx.x >> 6);
    if (node >= N) return;
    int lane = threadIdx.x & 63;
    int beg = rowptr[node], end = rowptr[node + 1];
    float a[8] = {0.f, 0.f, 0.f, 0.f, 0.f, 0.f, 0.f, 0.f};
    float b[8] = {0.f, 0.f, 0.f, 0.f, 0.f, 0.f, 0.f, 0.f};
    int j = beg;
    for (; j + 2 <= end; j += 2) {
        int s0 = __ldg(col + j);
        int s1 = __ldg(col + j + 1);
        uint4 v0 = ((const uint4*)(h + (size_t)s0 * H))[lane];
        uint4 v1 = ((const uint4*)(h + (size_t)s1 * H))[lane];
        const uint32_t* w0 = &v0.x;
        const uint32_t* w1 = &v1.x;
#pragma unroll
        for (int q = 0; q < 4; q++) {
            float2 p = __half22float2(*(__half2*)&w0[q]);
            float2 r = __half22float2(*(__half2*)&w1[q]);
            a[2 * q] += p.x; a[2 * q + 1] += p.y;
            b[2 * q] += r.x; b[2 * q + 1] += r.y;
        }
    }
    if (j < end) {
        int s0 = __ldg(col + j);
        uint4 v0 = ((const uint4*)(h + (size_t)s0 * H))[lane];
        const uint32_t* w0 = &v0.x;
#pragma unroll
        for (int q = 0; q < 4; q++) {
            float2 p = __half22float2(*(__half2*)&w0[q]);
            a[2 * q] += p.x; a[2 * q + 1] += p.y;
        }
    }
    uint4 o;
    uint32_t* ow = &o.x;
#pragma unroll
    for (int q = 0; q < 4; q++) {
        __half2 r = __floats2half2_rn(a[2 * q] + b[2 * q], a[2 * q + 1] + b[2 * q + 1]);
        ow[q] = *(uint32_t*)&r;
    }
    ((uint4*)(agg + (size_t)node * H))[lane] = o;
}

// ---------------------------------------------------------------------------
// g_Wt[mat][n][k] = fp16(W[mat][k][n])
__global__ void build_wt(const float* __restrict__ Wr, const float* __restrict__ Wn) {
    int mat = blockIdx.z;
    int l = mat >> 1, s = mat & 1;
    const float* W = (s ? Wn : Wr) + (size_t)l * H * H;
    __half* out = g_Wt + (size_t)mat * H * H;
    __shared__ float t[32][33];
    int kx = blockIdx.x * 32, ny = blockIdx.y * 32;
    int tx = threadIdx.x, ty = threadIdx.y;
#pragma unroll
    for (int j = 0; j < 4; j++)
        t[ty + j * 8][tx] = W[(size_t)(kx + ty + j * 8) * H + ny + tx];
    __syncthreads();
#pragma unroll
    for (int j = 0; j < 4; j++)
        out[(size_t)(ny + ty + j * 8) * H + kx + tx] = __float2half_rn(t[tx][ty + j * 8]);
}

// ---------------------------------------------------------------------------
// h0 = fp16(x @ W_in + b_in)
__global__ void in_gemm(const float* __restrict__ x, const float* __restrict__ Win,
                        const float* __restrict__ bin, __half* __restrict__ h, int N) {
    __shared__ float xs[16][17];
    int nb = blockIdx.x * 16;
    int tid = threadIdx.x;
    {
        int n = tid >> 4, k = tid & 15;
        int gn = nb + n;
        xs[n][k] = (gn < N) ? x[(size_t)gn * INF + k] : 0.f;
    }
    __syncthreads();
    float w0[16], w1[16];
#pragma unroll
    for (int k = 0; k < 16; k++) {
        w0[k] = Win[k * H + tid];
        w1[k] = Win[k * H + tid + 256];
    }
    float b0 = bin[tid], b1 = bin[tid + 256];
    for (int n = 0; n < 16; n++) {
        int gn = nb + n;
        if (gn >= N) break;
        float a0 = b0, a1 = b1;
#pragma unroll
        for (int k = 0; k < 16; k++) {
            float xv = xs[n][k];
            a0 += xv * w0[k];
            a1 += xv * w1[k];
        }
        h[(size_t)gn * H + tid]       = __float2half_rn(a0);
        h[(size_t)gn * H + tid + 256] = __float2half_rn(a1);
    }
}

// ---------------------------------------------------------------------------
// C = fp16(A1@W1' + A2@W2' + bias) via fp16 mma.sync m16n8k16 + ldmatrix
//   BM=128, BN=128, BK=32 halves, 8 warps (4x2), warp tile 32x64
//   SMEM rows: 32 halves (64B) padded to 20 words (80B) - conflict-free
//   5-stage cp.async pipeline (wait_group 3): 4 tile-loads in flight
#define BM 128
#define BN 128
#define BKT 32                                   // halves per K-tile
#define RSW 20                                   // words per row
#define TILE_WORDS (BM * RSW)                    // 2560 words = 10240 B
#define STAGES 5
#define CONV_SMEM (STAGES * 2 * TILE_WORDS * 4)  // 102400 B

__global__ __launch_bounds__(256, 2)
void conv_mma(const __half* __restrict__ A1, const __half* __restrict__ A2,
              const __half* __restrict__ Wt, const float* __restrict__ bias,
              __half* __restrict__ C, int M) {
    extern __shared__ uint32_t smw[];
    uint32_t* Asw = smw;                          // STAGES * TILE_WORDS
    uint32_t* Bsw = smw + STAGES * TILE_WORDS;
    uint32_t aAddr = smem_u32(Asw);
    uint32_t bAddr = smem_u32(Bsw);

    int tid = threadIdx.x;
    int wid = tid >> 5, lane = tid & 31;
    int g = lane >> 2, tig = lane & 3;
    int wm0 = (wid & 3) * 32;
    int wn0 = (wid >> 2) * 64;
    int m0 = blockIdx.x * BM;
    int n0 = blockIdx.y * BN;

    int cprow = tid >> 1;                         // 0..127
    int cpoff = (tid & 1) * 16;                   // halves offset: 0 or 16

    // ldmatrix per-lane source coordinates (within a k16 step at word kw):
    int aRow = lane & 15;
    int aColW = (lane >> 4) << 2;
    int bRow = (lane & 7) + ((lane >> 4) << 3);
    int bColW = ((lane >> 3) & 1) << 2;

    float acc[2][8][4];
#pragma unroll
    for (int i = 0; i < 2; i++)
#pragma unroll
        for (int j = 0; j < 8; j++)
#pragma unroll
            for (int q = 0; q < 4; q++) acc[i][j][q] = 0.f;

    const int NT = 32;                            // 2 sources * 16 K-tiles

    auto issue = [&](int t) {
        int st = t % STAGES;
        int s = t >> 4;
        int kt = (t & 15) * BKT;
        const __half* A = s ? A2 : A1;            // rows < NMAX always valid
        const __half* B = Wt + (size_t)s * H * H;
        uint32_t ab = aAddr + st * (TILE_WORDS * 4);
        uint32_t bb = bAddr + st * (TILE_WORDS * 4);
        uint32_t so = cprow * 80 + cpoff * 2;     // byte offset in tile
        const __half* ag = A + (size_t)(m0 + cprow) * H + kt + cpoff;
        const __half* bg = B + (size_t)(n0 + cprow) * H + kt + cpoff;
        cp_async16(ab + so,      ag);
        cp_async16(ab + so + 16, ag + 8);
        cp_async16(bb + so,      bg);
        cp_async16(bb + so + 16, bg + 8);
        asm volatile("cp.async.commit_group;" ::: "memory");
    };

    issue(0);
    issue(1);
    issue(2);
    issue(3);

    for (int t = 0; t < NT; t++) {
        if (t + 3 < NT) {
            asm volatile("cp.async.wait_group 3;" ::: "memory");
        } else {
            asm volatile("cp.async.wait_group 0;" ::: "memory");
        }
        __syncthreads();
        if (t + 4 < NT) issue(t + 4);

        uint32_t AsbA = aAddr + (t % STAGES) * (TILE_WORDS * 4);
        uint32_t BsbA = bAddr + (t % STAGES) * (TILE_WORDS * 4);
        uint32_t aBase = AsbA + (wm0 + aRow) * 80 + aColW * 4;
        uint32_t bBase = BsbA + (wn0 + bRow) * 80 + bColW * 4;
#pragma unroll
        for (int ks = 0; ks < 2; ks++) {
            uint32_t ko = ks * 32;                // k16 step = 8 words = 32 B
            uint32_t a[2][4], b[8][2];
#pragma unroll
            for (int i = 0; i < 2; i++)
                ldmatrix_x4(a[i][0], a[i][1], a[i][2], a[i][3],
                            aBase + ko + i * (16 * 80));
#pragma unroll
            for (int jp = 0; jp < 4; jp++)
                ldmatrix_x4(b[2 * jp][0], b[2 * jp][1], b[2 * jp + 1][0], b[2 * jp + 1][1],
                            bBase + ko + jp * (16 * 80));
#pragma unroll
            for (int i = 0; i < 2; i++)
#pragma unroll
                for (int j = 0; j < 8; j++)
                    mma_f16(acc[i][j], a[i], b[j]);
        }
    }

    // epilogue: add bias (fp32), store half2 pairs
#pragma unroll
    for (int i = 0; i < 2; i++) {
        int row0 = m0 + wm0 + i * 16 + g;
        int row1 = row0 + 8;
#pragma unroll
        for (int j = 0; j < 8; j++) {
            int col = n0 + wn0 + j * 8 + tig * 2;
            float bx = bias[col], by = bias[col + 1];
            if (row0 < M) {
                __half2 o = __floats2half2_rn(acc[i][j][0] + bx, acc[i][j][1] + by);
                *(__half2*)(C + (size_t)row0 * H + col) = o;
            }
            if (row1 < M) {
                __half2 o = __floats2half2_rn(acc[i][j][2] + bx, acc[i][j][3] + by);
                *(__half2*)(C + (size_t)row1 * H + col) = o;
            }
        }
    }
}

// ---------------------------------------------------------------------------
// In-place LayerNorm + ReLU per row (fp16 storage, fp32 math)
__global__ void ln_relu(__half* __restrict__ h, const float* __restrict__ gamma,
                        const float* __restrict__ beta, int N) {
    long row = blockIdx.x;
    if (row >= N) return;
    int tid = threadIdx.x;                        // 128 threads x 4 halves
    uint2 u = ((const uint2*)(h + row * H))[tid];
    float2 p0 = __half22float2(*(__half2*)&u.x);
    float2 p1 = __half22float2(*(__half2*)&u.y);
    float s  = p0.x + p0.y + p1.x + p1.y;
    float sq = p0.x * p0.x + p0.y * p0.y + p1.x * p1.x + p1.y * p1.y;
#pragma unroll
    for (int o = 16; o; o >>= 1) {
        s  += __shfl_xor_sync(~0u, s, o);
        sq += __shfl_xor_sync(~0u, sq, o);
    }
    __shared__ float ss[4], sqs[4];
    int w = tid >> 5;
    if ((tid & 31) == 0) { ss[w] = s; sqs[w] = sq; }
    __syncthreads();
    s  = ss[0] + ss[1] + ss[2] + ss[3];
    sq = sqs[0] + sqs[1] + sqs[2] + sqs[3];
    float mean = s * (1.f / H);
    float var  = sq * (1.f / H) - mean * mean;
    float rstd = rsqrtf(var + 1e-5f);
    int c = tid * 4;
    float4 gm = *(const float4*)(gamma + c);
    float4 bt = *(const float4*)(beta + c);
    float r0 = fmaxf((p0.x - mean) * rstd * gm.x + bt.x, 0.f);
    float r1 = fmaxf((p0.y - mean) * rstd * gm.y + bt.y, 0.f);
    float r2 = fmaxf((p1.x - mean) * rstd * gm.z + bt.z, 0.f);
    float r3 = fmaxf((p1.y - mean) * rstd * gm.w + bt.w, 0.f);
    __half2 o0 = __floats2half2_rn(r0, r1);
    __half2 o1 = __floats2half2_rn(r2, r3);
    uint2 o; o.x = *(uint32_t*)&o0; o.y = *(uint32_t*)&o1;
    ((uint2*)(h + row * H))[tid] = o;
}

// ---------------------------------------------------------------------------
__global__ void pool(const __half* __restrict__ h, const void* __restrict__ batch,
                     int N, const int* __restrict__ flag) {
    long n = blockIdx.x;
    if (n >= N) return;
    int f64 = flag[0];
    long g = ld_idx(batch, n, f64);
    int lane = threadIdx.x;                       // 128 threads x 4 halves
    uint2 u = ((const uint2*)(h + n * H))[lane];
    float2 p0 = __half22float2(*(__half2*)&u.x);
    float2 p1 = __half22float2(*(__half2*)&u.y);
    red_add_v4(g_pooled + g * H + 4 * lane, make_float4(p0.x, p0.y, p1.x, p1.y));
    if (lane == 0) atomicAdd(&g_counts[g], 1.f);
}

__global__ void out_gemm(const float* __restrict__ Wout, const float* __restrict__ bout,
                         float* __restrict__ out) {
    int g = blockIdx.x;
    __shared__ float ps[H];
    int tid = threadIdx.x;
    float inv = 1.f / fmaxf(g_counts[g], 1.f);
#pragma unroll
    for (int i = 0; i < 4; i++)
        ps[tid + i * 128] = g_pooled[(size_t)g * H + tid + i * 128] * inv;
    __syncthreads();
    float acc[4];
#pragma unroll
    for (int j = 0; j < 4; j++) acc[j] = bout[tid + j * 128];
    for (int k = 0; k < H; k++) {
        float p = ps[k];
#pragma unroll
        for (int j = 0; j < 4; j++)
            acc[j] += p * Wout[(size_t)k * H + tid + j * 128];
    }
#pragma unroll
    for (int j = 0; j < 4; j++) out[(size_t)g * H + tid + j * 128] = acc[j];
}

// ---------------------------------------------------------------------------
extern "C" void kernel_launch(void* const* d_in, const int* in_sizes, int n_in,
                              void* d_out, int out_size) {
    const float* x      = (const float*)d_in[0];
    const void*  ei     = d_in[1];
    const void*  batch  = d_in[2];
    const float* W_in   = (const float*)d_in[3];
    const float* b_in   = (const float*)d_in[4];
    const float* W_root = (const float*)d_in[5];
    const float* W_neigh= (const float*)d_in[6];
    const float* b_conv = (const float*)d_in[7];
    const float* ln_g   = (const float*)d_in[8];
    const float* ln_b   = (const float*)d_in[9];
    const float* W_out  = (const float*)d_in[10];
    const float* b_out  = (const float*)d_in[11];
    float* out = (float*)d_out;

    int N = in_sizes[0] / INF;
    int E = in_sizes[1] / 2;
    int G = out_size / H;
    int nchunks = (N + 1023) / 1024;

    void *pA, *pB, *pAgg, *pWt, *pPool, *pCnt, *pFlags;
    void *pDeg, *pRow, *pCur, *pCsums, *pCol;
    cudaGetSymbolAddress(&pA, g_hA);
    cudaGetSymbolAddress(&pB, g_hB);
    cudaGetSymbolAddress(&pAgg, g_agg);
    cudaGetSymbolAddress(&pWt, g_Wt);
    cudaGetSymbolAddress(&pPool, g_pooled);
    cudaGetSymbolAddress(&pCnt, g_counts);
    cudaGetSymbolAddress(&pFlags, g_flags);
    cudaGetSymbolAddress(&pDeg, g_deg);
    cudaGetSymbolAddress(&pRow, g_rowptr);
    cudaGetSymbolAddress(&pCur, g_cursor);
    cudaGetSymbolAddress(&pCsums, g_csums);
    cudaGetSymbolAddress(&pCol, g_col);
    __half* hA = (__half*)pA;
    __half* hB = (__half*)pB;
    int* flags = (int*)pFlags;

    cudaFuncSetAttribute(conv_mma, cudaFuncAttributeMaxDynamicSharedMemorySize, CONV_SMEM);

    cudaMemsetAsync(pFlags, 1, 2 * sizeof(int));
    {
        long nw = in_sizes[1];
        int blocks = (int)((nw / 2 + 255) / 256);
        detect_i64<<<blocks, 256>>>((const int*)ei, nw, flags + 0);
        nw = in_sizes[2];
        blocks = (int)((nw / 2 + 255) / 256);
        detect_i64<<<blocks, 256>>>((const int*)batch, nw, flags + 1);
    }

    // CSR build (once per call; graph identical across layers)
    cudaMemsetAsync(pDeg, 0, (size_t)N * sizeof(int));
    hist_dst<<<(E + 255) / 256, 256>>>(ei, E, flags, (int*)pDeg);
    chunk_sums<<<nchunks, 256>>>((const int*)pDeg, (int*)pCsums, N);
    scan_sums<<<1, 32>>>((int*)pCsums, (int*)pRow, nchunks, N, E);
    scan_chunks<<<nchunks, 1024>>>((const int*)pDeg, (const int*)pCsums,
                                   (int*)pRow, (int*)pCur, N);
    fill_csr<<<(E + 255) / 256, 256>>>(ei, E, flags, (int*)pCur, (int*)pCol);

    {
        dim3 g2(16, 16, 6);
        build_wt<<<g2, dim3(32, 8)>>>(W_root, W_neigh);
    }
    in_gemm<<<(N + 15) / 16, 256>>>(x, W_in, b_in, hA, N);

    __half* cur = hA;
    __half* nxt = hB;
    for (int l = 0; l < LAYERS; l++) {
        gather_sum<<<(N + 3) / 4, 256>>>(cur, (const int*)pRow, (const int*)pCol,
                                         (__half*)pAgg, N);
        dim3 grid((N + BM - 1) / BM, H / BN);
        conv_mma<<<grid, 256, CONV_SMEM>>>(cur, (const __half*)pAgg,
                                           (const __half*)pWt + (size_t)l * 2 * H * H,
                                           b_conv + (size_t)l * H, nxt, N);
        ln_relu<<<N, 128>>>(nxt, ln_g + (size_t)l * H, ln_b + (size_t)l * H, N);
        __half* t = cur; cur = nxt; nxt = t;
    }

    cudaMemsetAsync(pPool, 0, (size_t)G * H * sizeof(float));
    cudaMemsetAsync(pCnt, 0, G * sizeof(float));
    pool<<<N, 128>>>(cur, batch, N, flags + 1);
    out_gemm<<<G, 128>>>(W_out, b_out, out);
}

// round 14
// speedup vs baseline: 1.0188x; 1.0188x over previous
#include <cuda_runtime.h>
#include <cuda_fp16.h>
#include <cstdint>

// ---------------------------------------------------------------------------
// FragmentGraphEncoder: GNN forward
//   fp16 mma.sync (m16n8k16) conv GEMMs, BM=128 BN=128, 256 thr, ldmatrix
//   fragment loads, cp.async 4-stage pipeline (2 CTAs/SM), CSR aggregation
// ---------------------------------------------------------------------------

#define H 512
#define INF 16
#define LAYERS 3
#define NMAX 50176
#define GMAX 512
#define EMAX 1048576

__device__ __half g_hA[(size_t)NMAX * H];
__device__ __half g_hB[(size_t)NMAX * H];
__device__ __half g_agg[(size_t)NMAX * H];
__device__ __half g_Wt[(size_t)LAYERS * 2 * H * H];   // fp16, [n][k]
__device__ float  g_pooled[GMAX * H];
__device__ float  g_counts[GMAX];
__device__ int    g_flags[2];
// CSR scratch
__device__ int    g_deg[NMAX];
__device__ int    g_rowptr[NMAX + 1];
__device__ int    g_cursor[NMAX];
__device__ int    g_csums[64];
__device__ int    g_col[EMAX];

// ---------------------------------------------------------------------------
__device__ __forceinline__ void red_add_v4(float* addr, float4 v) {
    asm volatile("red.global.add.v4.f32 [%0], {%1, %2, %3, %4};"
                 :: "l"(addr), "f"(v.x), "f"(v.y), "f"(v.z), "f"(v.w) : "memory");
}
__device__ __forceinline__ void mma_f16(float* c, const uint32_t* a, const uint32_t* b) {
    asm("mma.sync.aligned.m16n8k16.row.col.f32.f16.f16.f32 "
        "{%0,%1,%2,%3}, {%4,%5,%6,%7}, {%8,%9}, {%0,%1,%2,%3};"
        : "+f"(c[0]), "+f"(c[1]), "+f"(c[2]), "+f"(c[3])
        : "r"(a[0]), "r"(a[1]), "r"(a[2]), "r"(a[3]), "r"(b[0]), "r"(b[1]));
}
__device__ __forceinline__ void ldmatrix_x4(uint32_t& r0, uint32_t& r1,
                                            uint32_t& r2, uint32_t& r3, uint32_t addr) {
    asm volatile("ldmatrix.sync.aligned.m8n8.x4.shared.b16 {%0,%1,%2,%3}, [%4];"
                 : "=r"(r0), "=r"(r1), "=r"(r2), "=r"(r3) : "r"(addr));
}
__device__ __forceinline__ uint32_t smem_u32(const void* p) {
    uint32_t a;
    asm("{ .reg .u64 t; cvta.to.shared.u64 t, %1; cvt.u32.u64 %0, t; }" : "=r"(a) : "l"(p));
    return a;
}
__device__ __forceinline__ void cp_async16(uint32_t dst, const void* src) {
    asm volatile("cp.async.cg.shared.global [%0], [%1], 16;" :: "r"(dst), "l"(src));
}

// Detect int64 vs int32 index buffers
__global__ void detect_i64(const int* __restrict__ w, long n_words, int* flag) {
    long i = (long)blockIdx.x * blockDim.x + threadIdx.x;
    long idx = 2 * i + 1;
    if (idx < n_words && w[idx] != 0) *flag = 0;
}
__device__ __forceinline__ long ld_idx(const void* p, long i, int f64) {
    return f64 ? (long)((const long long*)p)[i] : (long)((const int*)p)[i];
}

// ---------------------------------------------------------------------------
// CSR build (graph is layer-invariant: build once per call)
__global__ void hist_dst(const void* __restrict__ ei, int E,
                         const int* __restrict__ flag, int* __restrict__ deg) {
    int f64 = flag[0];
    int e = blockIdx.x * blockDim.x + threadIdx.x;
    if (e >= E) return;
    int dst = (int)ld_idx(ei, (long)E + e, f64);
    atomicAdd(&deg[dst], 1);
}

__global__ void chunk_sums(const int* __restrict__ deg, int* __restrict__ sums, int N) {
    __shared__ int ws[8];
    int base = blockIdx.x << 10;
    int tid = threadIdx.x;            // 256
    int v = 0;
#pragma unroll
    for (int i = 0; i < 4; i++) {
        int idx = base + tid + i * 256;
        v += (idx < N) ? deg[idx] : 0;
    }
#pragma unroll
    for (int o = 16; o; o >>= 1) v += __shfl_xor_sync(~0u, v, o);
    if ((tid & 31) == 0) ws[tid >> 5] = v;
    __syncthreads();
    if (tid == 0) {
        int s = 0;
#pragma unroll
        for (int i = 0; i < 8; i++) s += ws[i];
        sums[blockIdx.x] = s;
    }
}

__global__ void scan_sums(int* __restrict__ sums, int* __restrict__ rowptr,
                          int nchunks, int N, int E) {
    int lane = threadIdx.x;
    int v0 = (lane < nchunks) ? sums[lane] : 0;
    int v1 = (lane + 32 < nchunks) ? sums[lane + 32] : 0;
    int x0 = v0;
#pragma unroll
    for (int o = 1; o < 32; o <<= 1) {
        int t = __shfl_up_sync(~0u, x0, o);
        if (lane >= o) x0 += t;
    }
    int tot0 = __shfl_sync(~0u, x0, 31);
    int x1 = v1;
#pragma unroll
    for (int o = 1; o < 32; o <<= 1) {
        int t = __shfl_up_sync(~0u, x1, o);
        if (lane >= o) x1 += t;
    }
    x1 += tot0;
    if (lane < nchunks) sums[lane] = x0 - v0;
    if (lane + 32 < nchunks) sums[lane + 32] = x1 - v1;
    if (lane == 0) rowptr[N] = E;
}

__global__ void scan_chunks(const int* __restrict__ deg, const int* __restrict__ csums,
                            int* __restrict__ rowptr, int* __restrict__ cursor, int N) {
    __shared__ int wsum[32];
    int base = blockIdx.x << 10;
    int tid = threadIdx.x, lane = tid & 31, w = tid >> 5;
    int i = base + tid;
    int v = (i < N) ? deg[i] : 0;
    int x = v;
#pragma unroll
    for (int o = 1; o < 32; o <<= 1) {
        int t = __shfl_up_sync(~0u, x, o);
        if (lane >= o) x += t;
    }
    if (lane == 31) wsum[w] = x;
    __syncthreads();
    if (w == 0) {
        int s = wsum[lane];
#pragma unroll
        for (int o = 1; o < 32; o <<= 1) {
            int t = __shfl_up_sync(~0u, s, o);
            if (lane >= o) s += t;
        }
        wsum[lane] = s;
    }
    __syncthreads();
    int excl = x - v + (w ? wsum[w - 1] : 0) + csums[blockIdx.x];
    if (i < N) { rowptr[i] = excl; cursor[i] = excl; }
}

__global__ void fill_csr(const void* __restrict__ ei, int E,
                         const int* __restrict__ flag,
                         int* __restrict__ cursor, int* __restrict__ col) {
    int f64 = flag[0];
    int e = blockIdx.x * blockDim.x + threadIdx.x;
    if (e >= E) return;
    int src = (int)ld_idx(ei, e, f64);
    int dst = (int)ld_idx(ei, (long)E + e, f64);
    int pos = atomicAdd(&cursor[dst], 1);
    col[pos] = src;
}

// ---------------------------------------------------------------------------
// agg[n] = fp16(sum_{j in row n} h[col[j]])  — fp32 accumulation
// 4 nodes per 256-thread block; 64 threads/node, one uint4 (8 halves) each
__global__ void gather_sum(const __half* __restrict__ h, const int* __restrict__ rowptr,
                           const int* __restrict__ col, __half* __restrict__ agg, int N) {
    int node = blockIdx.x * 4 + (threadIdx.x >> 6);
    if (node >= N) return;
    int lane = threadIdx.x & 63;
    int beg = rowptr[node], end = rowptr[node + 1];
    float a[8] = {0.f, 0.f, 0.f, 0.f, 0.f, 0.f, 0.f, 0.f};
    float b[8] = {0.f, 0.f, 0.f, 0.f, 0.f, 0.f, 0.f, 0.f};
    int j = beg;
    for (; j + 2 <= end; j += 2) {
        int s0 = __ldg(col + j);
        int s1 = __ldg(col + j + 1);
        uint4 v0 = ((const uint4*)(h + (size_t)s0 * H))[lane];
        uint4 v1 = ((const uint4*)(h + (size_t)s1 * H))[lane];
        const uint32_t* w0 = &v0.x;
        const uint32_t* w1 = &v1.x;
#pragma unroll
        for (int q = 0; q < 4; q++) {
            float2 p = __half22float2(*(__half2*)&w0[q]);
            float2 r = __half22float2(*(__half2*)&w1[q]);
            a[2 * q] += p.x; a[2 * q + 1] += p.y;
            b[2 * q] += r.x; b[2 * q + 1] += r.y;
        }
    }
    if (j < end) {
        int s0 = __ldg(col + j);
        uint4 v0 = ((const uint4*)(h + (size_t)s0 * H))[lane];
        const uint32_t* w0 = &v0.x;
#pragma unroll
        for (int q = 0; q < 4; q++) {
            float2 p = __half22float2(*(__half2*)&w0[q]);
            a[2 * q] += p.x; a[2 * q + 1] += p.y;
        }
    }
    uint4 o;
    uint32_t* ow = &o.x;
#pragma unroll
    for (int q = 0; q < 4; q++) {
        __half2 r = __floats2half2_rn(a[2 * q] + b[2 * q], a[2 * q + 1] + b[2 * q + 1]);
        ow[q] = *(uint32_t*)&r;
    }
    ((uint4*)(agg + (size_t)node * H))[lane] = o;
}

// ---------------------------------------------------------------------------
// g_Wt[mat][n][k] = fp16(W[mat][k][n])
__global__ void build_wt(const float* __restrict__ Wr, const float* __restrict__ Wn) {
    int mat = blockIdx.z;
    int l = mat >> 1, s = mat & 1;
    const float* W = (s ? Wn : Wr) + (size_t)l * H * H;
    __half* out = g_Wt + (size_t)mat * H * H;
    __shared__ float t[32][33];
    int kx = blockIdx.x * 32, ny = blockIdx.y * 32;
    int tx = threadIdx.x, ty = threadIdx.y;
#pragma unroll
    for (int j = 0; j < 4; j++)
        t[ty + j * 8][tx] = W[(size_t)(kx + ty + j * 8) * H + ny + tx];
    __syncthreads();
#pragma unroll
    for (int j = 0; j < 4; j++)
        out[(size_t)(ny + ty + j * 8) * H + kx + tx] = __float2half_rn(t[tx][ty + j * 8]);
}

// ---------------------------------------------------------------------------
// h0 = fp16(x @ W_in + b_in)
__global__ void in_gemm(const float* __restrict__ x, const float* __restrict__ Win,
                        const float* __restrict__ bin, __half* __restrict__ h, int N) {
    __shared__ float xs[16][17];
    int nb = blockIdx.x * 16;
    int tid = threadIdx.x;
    {
        int n = tid >> 4, k = tid & 15;
        int gn = nb + n;
        xs[n][k] = (gn < N) ? x[(size_t)gn * INF + k] : 0.f;
    }
    __syncthreads();
    float w0[16], w1[16];
#pragma unroll
    for (int k = 0; k < 16; k++) {
        w0[k] = Win[k * H + tid];
        w1[k] = Win[k * H + tid + 256];
    }
    float b0 = bin[tid], b1 = bin[tid + 256];
    for (int n = 0; n < 16; n++) {
        int gn = nb + n;
        if (gn >= N) break;
        float a0 = b0, a1 = b1;
#pragma unroll
        for (int k = 0; k < 16; k++) {
            float xv = xs[n][k];
            a0 += xv * w0[k];
            a1 += xv * w1[k];
        }
        h[(size_t)gn * H + tid]       = __float2half_rn(a0);
        h[(size_t)gn * H + tid + 256] = __float2half_rn(a1);
    }
}

// ---------------------------------------------------------------------------
// C = fp16(A1@W1' + A2@W2' + bias) via fp16 mma.sync m16n8k16 + ldmatrix
//   BM=128, BN=128, BK=32 halves, 8 warps (4x2), warp tile 32x64
//   SMEM rows: 32 halves (64B) padded to 20 words (80B) - conflict-free
//   4-stage cp.async pipeline (wait_group 2), 2 CTAs/SM (163.8 KB total)
#define BM 128
#define BN 128
#define BKT 32                                   // halves per K-tile
#define RSW 20                                   // words per row
#define TILE_WORDS (BM * RSW)                    // 2560 words = 10240 B
#define STAGES 4
#define CONV_SMEM (STAGES * 2 * TILE_WORDS * 4)  // 81920 B

__global__ __launch_bounds__(256, 2)
void conv_mma(const __half* __restrict__ A1, const __half* __restrict__ A2,
              const __half* __restrict__ Wt, const float* __restrict__ bias,
              __half* __restrict__ C, int M) {
    extern __shared__ uint32_t smw[];
    uint32_t* Asw = smw;                          // STAGES * TILE_WORDS
    uint32_t* Bsw = smw + STAGES * TILE_WORDS;
    uint32_t aAddr = smem_u32(Asw);
    uint32_t bAddr = smem_u32(Bsw);

    int tid = threadIdx.x;
    int wid = tid >> 5, lane = tid & 31;
    int g = lane >> 2, tig = lane & 3;
    int wm0 = (wid & 3) * 32;
    int wn0 = (wid >> 2) * 64;
    int m0 = blockIdx.x * BM;
    int n0 = blockIdx.y * BN;

    int cprow = tid >> 1;                         // 0..127
    int cpoff = (tid & 1) * 16;                   // halves offset: 0 or 16

    // ldmatrix per-lane source coordinates (within a k16 step at word kw):
    int aRow = lane & 15;
    int aColW = (lane >> 4) << 2;
    int bRow = (lane & 7) + ((lane >> 4) << 3);
    int bColW = ((lane >> 3) & 1) << 2;

    float acc[2][8][4];
#pragma unroll
    for (int i = 0; i < 2; i++)
#pragma unroll
        for (int j = 0; j < 8; j++)
#pragma unroll
            for (int q = 0; q < 4; q++) acc[i][j][q] = 0.f;

    const int NT = 32;                            // 2 sources * 16 K-tiles

    auto issue = [&](int t) {
        int st = t % STAGES;
        int s = t >> 4;
        int kt = (t & 15) * BKT;
        const __half* A = s ? A2 : A1;            // rows < NMAX always valid
        const __half* B = Wt + (size_t)s * H * H;
        uint32_t ab = aAddr + st * (TILE_WORDS * 4);
        uint32_t bb = bAddr + st * (TILE_WORDS * 4);
        uint32_t so = cprow * 80 + cpoff * 2;     // byte offset in tile
        const __half* ag = A + (size_t)(m0 + cprow) * H + kt + cpoff;
        const __half* bg = B + (size_t)(n0 + cprow) * H + kt + cpoff;
        cp_async16(ab + so,      ag);
        cp_async16(ab + so + 16, ag + 8);
        cp_async16(bb + so,      bg);
        cp_async16(bb + so + 16, bg + 8);
        asm volatile("cp.async.commit_group;" ::: "memory");
    };

    issue(0);
    issue(1);
    issue(2);

    for (int t = 0; t < NT; t++) {
        if (t + 2 < NT) {
            asm volatile("cp.async.wait_group 2;" ::: "memory");
        } else {
            asm volatile("cp.async.wait_group 0;" ::: "memory");
        }
        __syncthreads();
        if (t + 3 < NT) issue(t + 3);

        uint32_t AsbA = aAddr + (t % STAGES) * (TILE_WORDS * 4);
        uint32_t BsbA = bAddr + (t % STAGES) * (TILE_WORDS * 4);
        uint32_t aBase = AsbA + (wm0 + aRow) * 80 + aColW * 4;
        uint32_t bBase = BsbA + (wn0 + bRow) * 80 + bColW * 4;
#pragma unroll
        for (int ks = 0; ks < 2; ks++) {
            uint32_t ko = ks * 32;                // k16 step = 8 words = 32 B
            uint32_t a[2][4], b[8][2];
#pragma unroll
            for (int i = 0; i < 2; i++)
                ldmatrix_x4(a[i][0], a[i][1], a[i][2], a[i][3],
                            aBase + ko + i * (16 * 80));
#pragma unroll
            for (int jp = 0; jp < 4; jp++)
                ldmatrix_x4(b[2 * jp][0], b[2 * jp][1], b[2 * jp + 1][0], b[2 * jp + 1][1],
                            bBase + ko + jp * (16 * 80));
#pragma unroll
            for (int i = 0; i < 2; i++)
#pragma unroll
                for (int j = 0; j < 8; j++)
                    mma_f16(acc[i][j], a[i], b[j]);
        }
    }

    // epilogue: add bias (fp32), store half2 pairs
#pragma unroll
    for (int i = 0; i < 2; i++) {
        int row0 = m0 + wm0 + i * 16 + g;
        int row1 = row0 + 8;
#pragma unroll
        for (int j = 0; j < 8; j++) {
            int col = n0 + wn0 + j * 8 + tig * 2;
            float bx = bias[col], by = bias[col + 1];
            if (row0 < M) {
                __half2 o = __floats2half2_rn(acc[i][j][0] + bx, acc[i][j][1] + by);
                *(__half2*)(C + (size_t)row0 * H + col) = o;
            }
            if (row1 < M) {
                __half2 o = __floats2half2_rn(acc[i][j][2] + bx, acc[i][j][3] + by);
                *(__half2*)(C + (size_t)row1 * H + col) = o;
            }
        }
    }
}

// ---------------------------------------------------------------------------
// In-place LayerNorm + ReLU per row (fp16 storage, fp32 math)
__global__ void ln_relu(__half* __restrict__ h, const float* __restrict__ gamma,
                        const float* __restrict__ beta, int N) {
    long row = blockIdx.x;
    if (row >= N) return;
    int tid = threadIdx.x;                        // 128 threads x 4 halves
    uint2 u = ((const uint2*)(h + row * H))[tid];
    float2 p0 = __half22float2(*(__half2*)&u.x);
    float2 p1 = __half22float2(*(__half2*)&u.y);
    float s  = p0.x + p0.y + p1.x + p1.y;
    float sq = p0.x * p0.x + p0.y * p0.y + p1.x * p1.x + p1.y * p1.y;
#pragma unroll
    for (int o = 16; o; o >>= 1) {
        s  += __shfl_xor_sync(~0u, s, o);
        sq += __shfl_xor_sync(~0u, sq, o);
    }
    __shared__ float ss[4], sqs[4];
    int w = tid >> 5;
    if ((tid & 31) == 0) { ss[w] = s; sqs[w] = sq; }
    __syncthreads();
    s  = ss[0] + ss[1] + ss[2] + ss[3];
    sq = sqs[0] + sqs[1] + sqs[2] + sqs[3];
    float mean = s * (1.f / H);
    float var  = sq * (1.f / H) - mean * mean;
    float rstd = rsqrtf(var + 1e-5f);
    int c = tid * 4;
    float4 gm = *(const float4*)(gamma + c);
    float4 bt = *(const float4*)(beta + c);
    float r0 = fmaxf((p0.x - mean) * rstd * gm.x + bt.x, 0.f);
    float r1 = fmaxf((p0.y - mean) * rstd * gm.y + bt.y, 0.f);
    float r2 = fmaxf((p1.x - mean) * rstd * gm.z + bt.z, 0.f);
    float r3 = fmaxf((p1.y - mean) * rstd * gm.w + bt.w, 0.f);
    __half2 o0 = __floats2half2_rn(r0, r1);
    __half2 o1 = __floats2half2_rn(r2, r3);
    uint2 o; o.x = *(uint32_t*)&o0; o.y = *(uint32_t*)&o1;
    ((uint2*)(h + row * H))[tid] = o;
}

// ---------------------------------------------------------------------------
__global__ void pool(const __half* __restrict__ h, const void* __restrict__ batch,
                     int N, const int* __restrict__ flag) {
    long n = blockIdx.x;
    if (n >= N) return;
    int f64 = flag[0];
    long g = ld_idx(batch, n, f64);
    int lane = threadIdx.x;                       // 128 threads x 4 halves
    uint2 u = ((const uint2*)(h + n * H))[lane];
    float2 p0 = __half22float2(*(__half2*)&u.x);
    float2 p1 = __half22float2(*(__half2*)&u.y);
    red_add_v4(g_pooled + g * H + 4 * lane, make_float4(p0.x, p0.y, p1.x, p1.y));
    if (lane == 0) atomicAdd(&g_counts[g], 1.f);
}

__global__ void out_gemm(const float* __restrict__ Wout, const float* __restrict__ bout,
                         float* __restrict__ out) {
    int g = blockIdx.x;
    __shared__ float ps[H];
    int tid = threadIdx.x;
    float inv = 1.f / fmaxf(g_counts[g], 1.f);
#pragma unroll
    for (int i = 0; i < 4; i++)
        ps[tid + i * 128] = g_pooled[(size_t)g * H + tid + i * 128] * inv;
    __syncthreads();
    float acc[4];
#pragma unroll
    for (int j = 0; j < 4; j++) acc[j] = bout[tid + j * 128];
    for (int k = 0; k < H; k++) {
        float p = ps[k];
#pragma unroll
        for (int j = 0; j < 4; j++)
            acc[j] += p * Wout[(size_t)k * H + tid + j * 128];
    }
#pragma unroll
    for (int j = 0; j < 4; j++) out[(size_t)g * H + tid + j * 128] = acc[j];
}

// ---------------------------------------------------------------------------
extern "C" void kernel_launch(void* const* d_in, const int* in_sizes, int n_in,
                              void* d_out, int out_size) {
    const float* x      = (const float*)d_in[0];
    const void*  ei     = d_in[1];
    const void*  batch  = d_in[2];
    const float* W_in   = (const float*)d_in[3];
    const float* b_in   = (const float*)d_in[4];
    const float* W_root = (const float*)d_in[5];
    const float* W_neigh= (const float*)d_in[6];
    const float* b_conv = (const float*)d_in[7];
    const float* ln_g   = (const float*)d_in[8];
    const float* ln_b   = (const float*)d_in[9];
    const float* W_out  = (const float*)d_in[10];
    const float* b_out  = (const float*)d_in[11];
    float* out = (float*)d_out;

    int N = in_sizes[0] / INF;
    int E = in_sizes[1] / 2;
    int G = out_size / H;
    int nchunks = (N + 1023) / 1024;

    void *pA, *pB, *pAgg, *pWt, *pPool, *pCnt, *pFlags;
    void *pDeg, *pRow, *pCur, *pCsums, *pCol;
    cudaGetSymbolAddress(&pA, g_hA);
    cudaGetSymbolAddress(&pB, g_hB);
    cudaGetSymbolAddress(&pAgg, g_agg);
    cudaGetSymbolAddress(&pWt, g_Wt);
    cudaGetSymbolAddress(&pPool, g_pooled);
    cudaGetSymbolAddress(&pCnt, g_counts);
    cudaGetSymbolAddress(&pFlags, g_flags);
    cudaGetSymbolAddress(&pDeg, g_deg);
    cudaGetSymbolAddress(&pRow, g_rowptr);
    cudaGetSymbolAddress(&pCur, g_cursor);
    cudaGetSymbolAddress(&pCsums, g_csums);
    cudaGetSymbolAddress(&pCol, g_col);
    __half* hA = (__half*)pA;
    __half* hB = (__half*)pB;
    int* flags = (int*)pFlags;

    cudaFuncSetAttribute(conv_mma, cudaFuncAttributeMaxDynamicSharedMemorySize, CONV_SMEM);

    cudaMemsetAsync(pFlags, 1, 2 * sizeof(int));
    {
        long nw = in_sizes[1];
        int blocks = (int)((nw / 2 + 255) / 256);
        detect_i64<<<blocks, 256>>>((const int*)ei, nw, flags + 0);
        nw = in_sizes[2];
        blocks = (int)((nw / 2 + 255) / 256);
        detect_i64<<<blocks, 256>>>((const int*)batch, nw, flags + 1);
    }

    // CSR build (once per call; graph identical across layers)
    cudaMemsetAsync(pDeg, 0, (size_t)N * sizeof(int));
    hist_dst<<<(E + 255) / 256, 256>>>(ei, E, flags, (int*)pDeg);
    chunk_sums<<<nchunks, 256>>>((const int*)pDeg, (int*)pCsums, N);
    scan_sums<<<1, 32>>>((int*)pCsums, (int*)pRow, nchunks, N, E);
    scan_chunks<<<nchunks, 1024>>>((const int*)pDeg, (const int*)pCsums,
                                   (int*)pRow, (int*)pCur, N);
    fill_csr<<<(E + 255) / 256, 256>>>(ei, E, flags, (int*)pCur, (int*)pCol);

    {
        dim3 g2(16, 16, 6);
        build_wt<<<g2, dim3(32, 8)>>>(W_root, W_neigh);
    }
    in_gemm<<<(N + 15) / 16, 256>>>(x, W_in, b_in, hA, N);

    __half* cur = hA;
    __half* nxt = hB;
    for (int l = 0; l < LAYERS; l++) {
        gather_sum<<<(N + 3) / 4, 256>>>(cur, (const int*)pRow, (const int*)pCol,
                                         (__half*)pAgg, N);
        dim3 grid((N + BM - 1) / BM, H / BN);
        conv_mma<<<grid, 256, CONV_SMEM>>>(cur, (const __half*)pAgg,
                                           (const __half*)pWt + (size_t)l * 2 * H * H,
                                           b_conv + (size_t)l * H, nxt, N);
        ln_relu<<<N, 128>>>(nxt, ln_g + (size_t)l * H, ln_b + (size_t)l * H, N);
        __half* t = cur; cur = nxt; nxt = t;
    }

    cudaMemsetAsync(pPool, 0, (size_t)G * H * sizeof(float));
    cudaMemsetAsync(pCnt, 0, G * sizeof(float));
    pool<<<N, 128>>>(cur, batch, N, flags + 1);
    out_gemm<<<G, 128>>>(W_out, b_out, out);
}

// round 15
// speedup vs baseline: 1.0433x; 1.0240x over previous
#include <cuda_runtime.h>
#include <cuda_fp16.h>
#include <cstdint>

// ---------------------------------------------------------------------------
// FragmentGraphEncoder: GNN forward
//   fp16 mma.sync (m16n8k16) conv GEMMs, BM=128 BN=128, 256 thr, ldmatrix
//   fragment loads, cp.async 3-stage pipeline (2 CTAs/SM), CSR aggregation
//   gather MLP=4, batched ln/pool
// ---------------------------------------------------------------------------

#define H 512
#define INF 16
#define LAYERS 3
#define NMAX 50176
#define GMAX 512
#define EMAX 1048576

__device__ __half g_hA[(size_t)NMAX * H];
__device__ __half g_hB[(size_t)NMAX * H];
__device__ __half g_agg[(size_t)NMAX * H];
__device__ __half g_Wt[(size_t)LAYERS * 2 * H * H];   // fp16, [n][k]
__device__ float  g_pooled[GMAX * H];
__device__ float  g_counts[GMAX];
__device__ int    g_flags[2];
// CSR scratch
__device__ int    g_deg[NMAX];
__device__ int    g_rowptr[NMAX + 1];
__device__ int    g_cursor[NMAX];
__device__ int    g_csums[64];
__device__ int    g_col[EMAX];

// ---------------------------------------------------------------------------
__device__ __forceinline__ void red_add_v4(float* addr, float4 v) {
    asm volatile("red.global.add.v4.f32 [%0], {%1, %2, %3, %4};"
                 :: "l"(addr), "f"(v.x), "f"(v.y), "f"(v.z), "f"(v.w) : "memory");
}
__device__ __forceinline__ void mma_f16(float* c, const uint32_t* a, const uint32_t* b) {
    asm("mma.sync.aligned.m16n8k16.row.col.f32.f16.f16.f32 "
        "{%0,%1,%2,%3}, {%4,%5,%6,%7}, {%8,%9}, {%0,%1,%2,%3};"
        : "+f"(c[0]), "+f"(c[1]), "+f"(c[2]), "+f"(c[3])
        : "r"(a[0]), "r"(a[1]), "r"(a[2]), "r"(a[3]), "r"(b[0]), "r"(b[1]));
}
__device__ __forceinline__ void ldmatrix_x4(uint32_t& r0, uint32_t& r1,
                                            uint32_t& r2, uint32_t& r3, uint32_t addr) {
    asm volatile("ldmatrix.sync.aligned.m8n8.x4.shared.b16 {%0,%1,%2,%3}, [%4];"
                 : "=r"(r0), "=r"(r1), "=r"(r2), "=r"(r3) : "r"(addr));
}
__device__ __forceinline__ uint32_t smem_u32(const void* p) {
    uint32_t a;
    asm("{ .reg .u64 t; cvta.to.shared.u64 t, %1; cvt.u32.u64 %0, t; }" : "=r"(a) : "l"(p));
    return a;
}
__device__ __forceinline__ void cp_async16(uint32_t dst, const void* src) {
    asm volatile("cp.async.cg.shared.global [%0], [%1], 16;" :: "r"(dst), "l"(src));
}

// Detect int64 vs int32 index buffers
__global__ void detect_i64(const int* __restrict__ w, long n_words, int* flag) {
    long i = (long)blockIdx.x * blockDim.x + threadIdx.x;
    long idx = 2 * i + 1;
    if (idx < n_words && w[idx] != 0) *flag = 0;
}
__device__ __forceinline__ long ld_idx(const void* p, long i, int f64) {
    return f64 ? (long)((const long long*)p)[i] : (long)((const int*)p)[i];
}

// ---------------------------------------------------------------------------
// CSR build (graph is layer-invariant: build once per call)
__global__ void hist_dst(const void* __restrict__ ei, int E,
                         const int* __restrict__ flag, int* __restrict__ deg) {
    int f64 = flag[0];
    int e = blockIdx.x * blockDim.x + threadIdx.x;
    if (e >= E) return;
    int dst = (int)ld_idx(ei, (long)E + e, f64);
    atomicAdd(&deg[dst], 1);
}

__global__ void chunk_sums(const int* __restrict__ deg, int* __restrict__ sums, int N) {
    __shared__ int ws[8];
    int base = blockIdx.x << 10;
    int tid = threadIdx.x;            // 256
    int v = 0;
#pragma unroll
    for (int i = 0; i < 4; i++) {
        int idx = base + tid + i * 256;
        v += (idx < N) ? deg[idx] : 0;
    }
#pragma unroll
    for (int o = 16; o; o >>= 1) v += __shfl_xor_sync(~0u, v, o);
    if ((tid & 31) == 0) ws[tid >> 5] = v;
    __syncthreads();
    if (tid == 0) {
        int s = 0;
#pragma unroll
        for (int i = 0; i < 8; i++) s += ws[i];
        sums[blockIdx.x] = s;
    }
}

__global__ void scan_sums(int* __restrict__ sums, int* __restrict__ rowptr,
                          int nchunks, int N, int E) {
    int lane = threadIdx.x;
    int v0 = (lane < nchunks) ? sums[lane] : 0;
    int v1 = (lane + 32 < nchunks) ? sums[lane + 32] : 0;
    int x0 = v0;
#pragma unroll
    for (int o = 1; o < 32; o <<= 1) {
        int t = __shfl_up_sync(~0u, x0, o);
        if (lane >= o) x0 += t;
    }
    int tot0 = __shfl_sync(~0u, x0, 31);
    int x1 = v1;
#pragma unroll
    for (int o = 1; o < 32; o <<= 1) {
        int t = __shfl_up_sync(~0u, x1, o);
        if (lane >= o) x1 += t;
    }
    x1 += tot0;
    if (lane < nchunks) sums[lane] = x0 - v0;
    if (lane + 32 < nchunks) sums[lane + 32] = x1 - v1;
    if (lane == 0) rowptr[N] = E;
}

__global__ void scan_chunks(const int* __restrict__ deg, const int* __restrict__ csums,
                            int* __restrict__ rowptr, int* __restrict__ cursor, int N) {
    __shared__ int wsum[32];
    int base = blockIdx.x << 10;
    int tid = threadIdx.x, lane = tid & 31, w = tid >> 5;
    int i = base + tid;
    int v = (i < N) ? deg[i] : 0;
    int x = v;
#pragma unroll
    for (int o = 1; o < 32; o <<= 1) {
        int t = __shfl_up_sync(~0u, x, o);
        if (lane >= o) x += t;
    }
    if (lane == 31) wsum[w] = x;
    __syncthreads();
    if (w == 0) {
        int s = wsum[lane];
#pragma unroll
        for (int o = 1; o < 32; o <<= 1) {
            int t = __shfl_up_sync(~0u, s, o);
            if (lane >= o) s += t;
        }
        wsum[lane] = s;
    }
    __syncthreads();
    int excl = x - v + (w ? wsum[w - 1] : 0) + csums[blockIdx.x];
    if (i < N) { rowptr[i] = excl; cursor[i] = excl; }
}

__global__ void fill_csr(const void* __restrict__ ei, int E,
                         const int* __restrict__ flag,
                         int* __restrict__ cursor, int* __restrict__ col) {
    int f64 = flag[0];
    int e = blockIdx.x * blockDim.x + threadIdx.x;
    if (e >= E) return;
    int src = (int)ld_idx(ei, e, f64);
    int dst = (int)ld_idx(ei, (long)E + e, f64);
    int pos = atomicAdd(&cursor[dst], 1);
    col[pos] = src;
}

// ---------------------------------------------------------------------------
// agg[n] = fp16(sum_{j in row n} h[col[j]])  — fp32 accumulation, MLP=4
// 4 nodes per 256-thread block; 64 threads/node, one uint4 (8 halves) each
__global__ void gather_sum(const __half* __restrict__ h, const int* __restrict__ rowptr,
                           const int* __restrict__ col, __half* __restrict__ agg, int N) {
    int node = blockIdx.x * 4 + (threadIdx.x >> 6);
    if (node >= N) return;
    int lane = threadIdx.x & 63;
    int beg = rowptr[node], end = rowptr[node + 1];
    float a[8] = {0.f, 0.f, 0.f, 0.f, 0.f, 0.f, 0.f, 0.f};
    float b[8] = {0.f, 0.f, 0.f, 0.f, 0.f, 0.f, 0.f, 0.f};
    int j = beg;
    for (; j + 4 <= end; j += 4) {
        int s0 = __ldg(col + j);
        int s1 = __ldg(col + j + 1);
        int s2 = __ldg(col + j + 2);
        int s3 = __ldg(col + j + 3);
        uint4 v0 = ((const uint4*)(h + (size_t)s0 * H))[lane];
        uint4 v1 = ((const uint4*)(h + (size_t)s1 * H))[lane];
        uint4 v2 = ((const uint4*)(h + (size_t)s2 * H))[lane];
        uint4 v3 = ((const uint4*)(h + (size_t)s3 * H))[lane];
        const uint32_t* w0 = &v0.x;
        const uint32_t* w1 = &v1.x;
        const uint32_t* w2 = &v2.x;
        const uint32_t* w3 = &v3.x;
#pragma unroll
        for (int q = 0; q < 4; q++) {
            float2 p = __half22float2(*(__half2*)&w0[q]);
            float2 r = __half22float2(*(__half2*)&w1[q]);
            float2 u = __half22float2(*(__half2*)&w2[q]);
            float2 t = __half22float2(*(__half2*)&w3[q]);
            a[2 * q] += p.x + u.x; a[2 * q + 1] += p.y + u.y;
            b[2 * q] += r.x + t.x; b[2 * q + 1] += r.y + t.y;
        }
    }
    for (; j < end; j++) {
        int s0 = __ldg(col + j);
        uint4 v0 = ((const uint4*)(h + (size_t)s0 * H))[lane];
        const uint32_t* w0 = &v0.x;
#pragma unroll
        for (int q = 0; q < 4; q++) {
            float2 p = __half22float2(*(__half2*)&w0[q]);
            a[2 * q] += p.x; a[2 * q + 1] += p.y;
        }
    }
    uint4 o;
    uint32_t* ow = &o.x;
#pragma unroll
    for (int q = 0; q < 4; q++) {
        __half2 r = __floats2half2_rn(a[2 * q] + b[2 * q], a[2 * q + 1] + b[2 * q + 1]);
        ow[q] = *(uint32_t*)&r;
    }
    ((uint4*)(agg + (size_t)node * H))[lane] = o;
}

// ---------------------------------------------------------------------------
// g_Wt[mat][n][k] = fp16(W[mat][k][n])
__global__ void build_wt(const float* __restrict__ Wr, const float* __restrict__ Wn) {
    int mat = blockIdx.z;
    int l = mat >> 1, s = mat & 1;
    const float* W = (s ? Wn : Wr) + (size_t)l * H * H;
    __half* out = g_Wt + (size_t)mat * H * H;
    __shared__ float t[32][33];
    int kx = blockIdx.x * 32, ny = blockIdx.y * 32;
    int tx = threadIdx.x, ty = threadIdx.y;
#pragma unroll
    for (int j = 0; j < 4; j++)
        t[ty + j * 8][tx] = W[(size_t)(kx + ty + j * 8) * H + ny + tx];
    __syncthreads();
#pragma unroll
    for (int j = 0; j < 4; j++)
        out[(size_t)(ny + ty + j * 8) * H + kx + tx] = __float2half_rn(t[tx][ty + j * 8]);
}

// ---------------------------------------------------------------------------
// h0 = fp16(x @ W_in + b_in)
__global__ void in_gemm(const float* __restrict__ x, const float* __restrict__ Win,
                        const float* __restrict__ bin, __half* __restrict__ h, int N) {
    __shared__ float xs[16][17];
    int nb = blockIdx.x * 16;
    int tid = threadIdx.x;
    {
        int n = tid >> 4, k = tid & 15;
        int gn = nb + n;
        xs[n][k] = (gn < N) ? x[(size_t)gn * INF + k] : 0.f;
    }
    __syncthreads();
    float w0[16], w1[16];
#pragma unroll
    for (int k = 0; k < 16; k++) {
        w0[k] = Win[k * H + tid];
        w1[k] = Win[k * H + tid + 256];
    }
    float b0 = bin[tid], b1 = bin[tid + 256];
    for (int n = 0; n < 16; n++) {
        int gn = nb + n;
        if (gn >= N) break;
        float a0 = b0, a1 = b1;
#pragma unroll
        for (int k = 0; k < 16; k++) {
            float xv = xs[n][k];
            a0 += xv * w0[k];
            a1 += xv * w1[k];
        }
        h[(size_t)gn * H + tid]       = __float2half_rn(a0);
        h[(size_t)gn * H + tid + 256] = __float2half_rn(a1);
    }
}

// ---------------------------------------------------------------------------
// C = fp16(A1@W1' + A2@W2' + bias) via fp16 mma.sync m16n8k16 + ldmatrix
//   BM=128, BN=128, BK=32 halves, 8 warps (4x2), warp tile 32x64
//   3-stage cp.async pipeline, 2 CTAs/SM  (R12 proven config)
#define BM 128
#define BN 128
#define BKT 32                                   // halves per K-tile
#define RSW 20                                   // words per row
#define TILE_WORDS (BM * RSW)                    // 2560 words = 10240 B
#define STAGES 3
#define CONV_SMEM (STAGES * 2 * TILE_WORDS * 4)  // 61440 B

__global__ __launch_bounds__(256, 2)
void conv_mma(const __half* __restrict__ A1, const __half* __restrict__ A2,
              const __half* __restrict__ Wt, const float* __restrict__ bias,
              __half* __restrict__ C, int M) {
    extern __shared__ uint32_t smw[];
    uint32_t* Asw = smw;                          // STAGES * TILE_WORDS
    uint32_t* Bsw = smw + STAGES * TILE_WORDS;
    uint32_t aAddr = smem_u32(Asw);
    uint32_t bAddr = smem_u32(Bsw);

    int tid = threadIdx.x;
    int wid = tid >> 5, lane = tid & 31;
    int g = lane >> 2, tig = lane & 3;
    int wm0 = (wid & 3) * 32;
    int wn0 = (wid >> 2) * 64;
    int m0 = blockIdx.x * BM;
    int n0 = blockIdx.y * BN;

    int cprow = tid >> 1;                         // 0..127
    int cpoff = (tid & 1) * 16;                   // halves offset: 0 or 16

    int aRow = lane & 15;
    int aColW = (lane >> 4) << 2;
    int bRow = (lane & 7) + ((lane >> 4) << 3);
    int bColW = ((lane >> 3) & 1) << 2;

    float acc[2][8][4];
#pragma unroll
    for (int i = 0; i < 2; i++)
#pragma unroll
        for (int j = 0; j < 8; j++)
#pragma unroll
            for (int q = 0; q < 4; q++) acc[i][j][q] = 0.f;

    const int NT = 32;                            // 2 sources * 16 K-tiles

    auto issue = [&](int t) {
        int st = t % STAGES;
        int s = t >> 4;
        int kt = (t & 15) * BKT;
        const __half* A = s ? A2 : A1;            // rows < NMAX always valid
        const __half* B = Wt + (size_t)s * H * H;
        uint32_t ab = aAddr + st * (TILE_WORDS * 4);
        uint32_t bb = bAddr + st * (TILE_WORDS * 4);
        uint32_t so = cprow * 80 + cpoff * 2;     // byte offset in tile
        const __half* ag = A + (size_t)(m0 + cprow) * H + kt + cpoff;
        const __half* bg = B + (size_t)(n0 + cprow) * H + kt + cpoff;
        cp_async16(ab + so,      ag);
        cp_async16(ab + so + 16, ag + 8);
        cp_async16(bb + so,      bg);
        cp_async16(bb + so + 16, bg + 8);
        asm volatile("cp.async.commit_group;" ::: "memory");
    };

    issue(0);
    issue(1);

    for (int t = 0; t < NT; t++) {
        if (t + 1 < NT) {
            asm volatile("cp.async.wait_group 1;" ::: "memory");
        } else {
            asm volatile("cp.async.wait_group 0;" ::: "memory");
        }
        __syncthreads();
        if (t + 2 < NT) issue(t + 2);

        uint32_t AsbA = aAddr + (t % STAGES) * (TILE_WORDS * 4);
        uint32_t BsbA = bAddr + (t % STAGES) * (TILE_WORDS * 4);
        uint32_t aBase = AsbA + (wm0 + aRow) * 80 + aColW * 4;
        uint32_t bBase = BsbA + (wn0 + bRow) * 80 + bColW * 4;
#pragma unroll
        for (int ks = 0; ks < 2; ks++) {
            uint32_t ko = ks * 32;                // k16 step = 8 words = 32 B
            uint32_t a[2][4], b[8][2];
#pragma unroll
            for (int i = 0; i < 2; i++)
                ldmatrix_x4(a[i][0], a[i][1], a[i][2], a[i][3],
                            aBase + ko + i * (16 * 80));
#pragma unroll
            for (int jp = 0; jp < 4; jp++)
                ldmatrix_x4(b[2 * jp][0], b[2 * jp][1], b[2 * jp + 1][0], b[2 * jp + 1][1],
                            bBase + ko + jp * (16 * 80));
#pragma unroll
            for (int i = 0; i < 2; i++)
#pragma unroll
                for (int j = 0; j < 8; j++)
                    mma_f16(acc[i][j], a[i], b[j]);
        }
    }

    // epilogue: add bias (fp32), store half2 pairs
#pragma unroll
    for (int i = 0; i < 2; i++) {
        int row0 = m0 + wm0 + i * 16 + g;
        int row1 = row0 + 8;
#pragma unroll
        for (int j = 0; j < 8; j++) {
            int col = n0 + wn0 + j * 8 + tig * 2;
            float bx = bias[col], by = bias[col + 1];
            if (row0 < M) {
                __half2 o = __floats2half2_rn(acc[i][j][0] + bx, acc[i][j][1] + by);
                *(__half2*)(C + (size_t)row0 * H + col) = o;
            }
            if (row1 < M) {
                __half2 o = __floats2half2_rn(acc[i][j][2] + bx, acc[i][j][3] + by);
                *(__half2*)(C + (size_t)row1 * H + col) = o;
            }
        }
    }
}

// ---------------------------------------------------------------------------
// In-place LayerNorm + ReLU; 2 rows per 256-thread block (fp16 storage)
__global__ void ln_relu(__half* __restrict__ h, const float* __restrict__ gamma,
                        const float* __restrict__ beta, int N) {
    long row = blockIdx.x * 2 + (threadIdx.x >> 7);
    if (row >= N) return;
    int tid = threadIdx.x & 127;                  // 128 threads x 4 halves
    int grp = threadIdx.x >> 7;
    uint2 u = ((const uint2*)(h + row * H))[tid];
    float2 p0 = __half22float2(*(__half2*)&u.x);
    float2 p1 = __half22float2(*(__half2*)&u.y);
    float s  = p0.x + p0.y + p1.x + p1.y;
    float sq = p0.x * p0.x + p0.y * p0.y + p1.x * p1.x + p1.y * p1.y;
#pragma unroll
    for (int o = 16; o; o >>= 1) {
        s  += __shfl_xor_sync(~0u, s, o);
        sq += __shfl_xor_sync(~0u, sq, o);
    }
    __shared__ float ss[2][4], sqs[2][4];
    int w = tid >> 5;
    if ((tid & 31) == 0) { ss[grp][w] = s; sqs[grp][w] = sq; }
    __syncthreads();
    s  = ss[grp][0] + ss[grp][1] + ss[grp][2] + ss[grp][3];
    sq = sqs[grp][0] + sqs[grp][1] + sqs[grp][2] + sqs[grp][3];
    float mean = s * (1.f / H);
    float var  = sq * (1.f / H) - mean * mean;
    float rstd = rsqrtf(var + 1e-5f);
    int c = tid * 4;
    float4 gm = *(const float4*)(gamma + c);
    float4 bt = *(const float4*)(beta + c);
    float r0 = fmaxf((p0.x - mean) * rstd * gm.x + bt.x, 0.f);
    float r1 = fmaxf((p0.y - mean) * rstd * gm.y + bt.y, 0.f);
    float r2 = fmaxf((p1.x - mean) * rstd * gm.z + bt.z, 0.f);
    float r3 = fmaxf((p1.y - mean) * rstd * gm.w + bt.w, 0.f);
    __half2 o0 = __floats2half2_rn(r0, r1);
    __half2 o1 = __floats2half2_rn(r2, r3);
    uint2 o; o.x = *(uint32_t*)&o0; o.y = *(uint32_t*)&o1;
    ((uint2*)(h + row * H))[tid] = o;
}

// ---------------------------------------------------------------------------
// pool: 4 nodes per 256-thread block; 64 threads/node, uint4 per thread
__global__ void pool(const __half* __restrict__ h, const void* __restrict__ batch,
                     int N, const int* __restrict__ flag) {
    long n = blockIdx.x * 4 + (threadIdx.x >> 6);
    if (n >= N) return;
    int f64 = flag[0];
    long g = ld_idx(batch, n, f64);
    int lane = threadIdx.x & 63;                  // 64 threads x 8 halves
    uint4 u = ((const uint4*)(h + n * H))[lane];
    const uint32_t* w = &u.x;
    float2 p0 = __half22float2(*(__half2*)&w[0]);
    float2 p1 = __half22float2(*(__half2*)&w[1]);
    float2 p2 = __half22float2(*(__half2*)&w[2]);
    float2 p3 = __half22float2(*(__half2*)&w[3]);
    float* dst = g_pooled + g * H + 8 * lane;
    red_add_v4(dst,     make_float4(p0.x, p0.y, p1.x, p1.y));
    red_add_v4(dst + 4, make_float4(p2.x, p2.y, p3.x, p3.y));
    if (lane == 0) atomicAdd(&g_counts[g], 1.f);
}

__global__ void out_gemm(const float* __restrict__ Wout, const float* __restrict__ bout,
                         float* __restrict__ out) {
    int g = blockIdx.x;
    __shared__ float ps[H];
    int tid = threadIdx.x;
    float inv = 1.f / fmaxf(g_counts[g], 1.f);
#pragma unroll
    for (int i = 0; i < 4; i++)
        ps[tid + i * 128] = g_pooled[(size_t)g * H + tid + i * 128] * inv;
    __syncthreads();
    float acc[4];
#pragma unroll
    for (int j = 0; j < 4; j++) acc[j] = bout[tid + j * 128];
    for (int k = 0; k < H; k++) {
        float p = ps[k];
#pragma unroll
        for (int j = 0; j < 4; j++)
            acc[j] += p * Wout[(size_t)k * H + tid + j * 128];
    }
#pragma unroll
    for (int j = 0; j < 4; j++) out[(size_t)g * H + tid + j * 128] = acc[j];
}

// ---------------------------------------------------------------------------
extern "C" void kernel_launch(void* const* d_in, const int* in_sizes, int n_in,
                              void* d_out, int out_size) {
    const float* x      = (const float*)d_in[0];
    const void*  ei     = d_in[1];
    const void*  batch  = d_in[2];
    const float* W_in   = (const float*)d_in[3];
    const float* b_in   = (const float*)d_in[4];
    const float* W_root = (const float*)d_in[5];
    const float* W_neigh= (const float*)d_in[6];
    const float* b_conv = (const float*)d_in[7];
    const float* ln_g   = (const float*)d_in[8];
    const float* ln_b   = (const float*)d_in[9];
    const float* W_out  = (const float*)d_in[10];
    const float* b_out  = (const float*)d_in[11];
    float* out = (float*)d_out;

    int N = in_sizes[0] / INF;
    int E = in_sizes[1] / 2;
    int G = out_size / H;
    int nchunks = (N + 1023) / 1024;

    void *pA, *pB, *pAgg, *pWt, *pPool, *pCnt, *pFlags;
    void *pDeg, *pRow, *pCur, *pCsums, *pCol;
    cudaGetSymbolAddress(&pA, g_hA);
    cudaGetSymbolAddress(&pB, g_hB);
    cudaGetSymbolAddress(&pAgg, g_agg);
    cudaGetSymbolAddress(&pWt, g_Wt);
    cudaGetSymbolAddress(&pPool, g_pooled);
    cudaGetSymbolAddress(&pCnt, g_counts);
    cudaGetSymbolAddress(&pFlags, g_flags);
    cudaGetSymbolAddress(&pDeg, g_deg);
    cudaGetSymbolAddress(&pRow, g_rowptr);
    cudaGetSymbolAddress(&pCur, g_cursor);
    cudaGetSymbolAddress(&pCsums, g_csums);
    cudaGetSymbolAddress(&pCol, g_col);
    __half* hA = (__half*)pA;
    __half* hB = (__half*)pB;
    int* flags = (int*)pFlags;

    cudaFuncSetAttribute(conv_mma, cudaFuncAttributeMaxDynamicSharedMemorySize, CONV_SMEM);

    cudaMemsetAsync(pFlags, 1, 2 * sizeof(int));
    {
        long nw = in_sizes[1];
        int blocks = (int)((nw / 2 + 255) / 256);
        detect_i64<<<blocks, 256>>>((const int*)ei, nw, flags + 0);
        nw = in_sizes[2];
        blocks = (int)((nw / 2 + 255) / 256);
        detect_i64<<<blocks, 256>>>((const int*)batch, nw, flags + 1);
    }

    // CSR build (once per call; graph identical across layers)
    cudaMemsetAsync(pDeg, 0, (size_t)N * sizeof(int));
    hist_dst<<<(E + 255) / 256, 256>>>(ei, E, flags, (int*)pDeg);
    chunk_sums<<<nchunks, 256>>>((const int*)pDeg, (int*)pCsums, N);
    scan_sums<<<1, 32>>>((int*)pCsums, (int*)pRow, nchunks, N, E);
    scan_chunks<<<nchunks, 1024>>>((const int*)pDeg, (const int*)pCsums,
                                   (int*)pRow, (int*)pCur, N);
    fill_csr<<<(E + 255) / 256, 256>>>(ei, E, flags, (int*)pCur, (int*)pCol);

    {
        dim3 g2(16, 16, 6);
        build_wt<<<g2, dim3(32, 8)>>>(W_root, W_neigh);
    }
    in_gemm<<<(N + 15) / 16, 256>>>(x, W_in, b_in, hA, N);

    __half* cur = hA;
    __half* nxt = hB;
    for (int l = 0; l < LAYERS; l++) {
        gather_sum<<<(N + 3) / 4, 256>>>(cur, (const int*)pRow, (const int*)pCol,
                                         (__half*)pAgg, N);
        dim3 grid((N + BM - 1) / BM, H / BN);
        conv_mma<<<grid, 256, CONV_SMEM>>>(cur, (const __half*)pAgg,
                                           (const __half*)pWt + (size_t)l * 2 * H * H,
                                           b_conv + (size_t)l * H, nxt, N);
        ln_relu<<<(N + 1) / 2, 256>>>(nxt, ln_g + (size_t)l * H, ln_b + (size_t)l * H, N);
        __half* t = cur; cur = nxt; nxt = t;
    }

    cudaMemsetAsync(pPool, 0, (size_t)G * H * sizeof(float));
    cudaMemsetAsync(pCnt, 0, G * sizeof(float));
    pool<<<(N + 3) / 4, 256>>>(cur, batch, N, flags + 1);
    out_gemm<<<G, 128>>>(W_out, b_out, out);
}

// round 16
// speedup vs baseline: 1.0535x; 1.0098x over previous
#include <cuda_runtime.h>
#include <cuda_fp16.h>
#include <cstdint>

// ---------------------------------------------------------------------------
// FragmentGraphEncoder: GNN forward
//   fp16 mma.sync (m16n8k16) conv GEMMs, BM=128 BN=128, 256 thr, ldmatrix
//   fragment loads, cp.async 3-stage pipeline (2 CTAs/SM), CSR aggregation
//   (gather MLP=2 as in R12), batched ln/pool
// ---------------------------------------------------------------------------

#define H 512
#define INF 16
#define LAYERS 3
#define NMAX 50176
#define GMAX 512
#define EMAX 1048576

__device__ __half g_hA[(size_t)NMAX * H];
__device__ __half g_hB[(size_t)NMAX * H];
__device__ __half g_agg[(size_t)NMAX * H];
__device__ __half g_Wt[(size_t)LAYERS * 2 * H * H];   // fp16, [n][k]
__device__ float  g_pooled[GMAX * H];
__device__ float  g_counts[GMAX];
__device__ int    g_flags[2];
// CSR scratch
__device__ int    g_deg[NMAX];
__device__ int    g_rowptr[NMAX + 1];
__device__ int    g_cursor[NMAX];
__device__ int    g_csums[64];
__device__ int    g_col[EMAX];

// ---------------------------------------------------------------------------
__device__ __forceinline__ void red_add_v4(float* addr, float4 v) {
    asm volatile("red.global.add.v4.f32 [%0], {%1, %2, %3, %4};"
                 :: "l"(addr), "f"(v.x), "f"(v.y), "f"(v.z), "f"(v.w) : "memory");
}
__device__ __forceinline__ void mma_f16(float* c, const uint32_t* a, const uint32_t* b) {
    asm("mma.sync.aligned.m16n8k16.row.col.f32.f16.f16.f32 "
        "{%0,%1,%2,%3}, {%4,%5,%6,%7}, {%8,%9}, {%0,%1,%2,%3};"
        : "+f"(c[0]), "+f"(c[1]), "+f"(c[2]), "+f"(c[3])
        : "r"(a[0]), "r"(a[1]), "r"(a[2]), "r"(a[3]), "r"(b[0]), "r"(b[1]));
}
__device__ __forceinline__ void ldmatrix_x4(uint32_t& r0, uint32_t& r1,
                                            uint32_t& r2, uint32_t& r3, uint32_t addr) {
    asm volatile("ldmatrix.sync.aligned.m8n8.x4.shared.b16 {%0,%1,%2,%3}, [%4];"
                 : "=r"(r0), "=r"(r1), "=r"(r2), "=r"(r3) : "r"(addr));
}
__device__ __forceinline__ uint32_t smem_u32(const void* p) {
    uint32_t a;
    asm("{ .reg .u64 t; cvta.to.shared.u64 t, %1; cvt.u32.u64 %0, t; }" : "=r"(a) : "l"(p));
    return a;
}
__device__ __forceinline__ void cp_async16(uint32_t dst, const void* src) {
    asm volatile("cp.async.cg.shared.global [%0], [%1], 16;" :: "r"(dst), "l"(src));
}

// Detect int64 vs int32 index buffers
__global__ void detect_i64(const int* __restrict__ w, long n_words, int* flag) {
    long i = (long)blockIdx.x * blockDim.x + threadIdx.x;
    long idx = 2 * i + 1;
    if (idx < n_words && w[idx] != 0) *flag = 0;
}
__device__ __forceinline__ long ld_idx(const void* p, long i, int f64) {
    return f64 ? (long)((const long long*)p)[i] : (long)((const int*)p)[i];
}

// ---------------------------------------------------------------------------
// CSR build (graph is layer-invariant: build once per call)
__global__ void hist_dst(const void* __restrict__ ei, int E,
                         const int* __restrict__ flag, int* __restrict__ deg) {
    int f64 = flag[0];
    int e = blockIdx.x * blockDim.x + threadIdx.x;
    if (e >= E) return;
    int dst = (int)ld_idx(ei, (long)E + e, f64);
    atomicAdd(&deg[dst], 1);
}

__global__ void chunk_sums(const int* __restrict__ deg, int* __restrict__ sums, int N) {
    __shared__ int ws[8];
    int base = blockIdx.x << 10;
    int tid = threadIdx.x;            // 256
    int v = 0;
#pragma unroll
    for (int i = 0; i < 4; i++) {
        int idx = base + tid + i * 256;
        v += (idx < N) ? deg[idx] : 0;
    }
#pragma unroll
    for (int o = 16; o; o >>= 1) v += __shfl_xor_sync(~0u, v, o);
    if ((tid & 31) == 0) ws[tid >> 5] = v;
    __syncthreads();
    if (tid == 0) {
        int s = 0;
#pragma unroll
        for (int i = 0; i < 8; i++) s += ws[i];
        sums[blockIdx.x] = s;
    }
}

__global__ void scan_sums(int* __restrict__ sums, int* __restrict__ rowptr,
                          int nchunks, int N, int E) {
    int lane = threadIdx.x;
    int v0 = (lane < nchunks) ? sums[lane] : 0;
    int v1 = (lane + 32 < nchunks) ? sums[lane + 32] : 0;
    int x0 = v0;
#pragma unroll
    for (int o = 1; o < 32; o <<= 1) {
        int t = __shfl_up_sync(~0u, x0, o);
        if (lane >= o) x0 += t;
    }
    int tot0 = __shfl_sync(~0u, x0, 31);
    int x1 = v1;
#pragma unroll
    for (int o = 1; o < 32; o <<= 1) {
        int t = __shfl_up_sync(~0u, x1, o);
        if (lane >= o) x1 += t;
    }
    x1 += tot0;
    if (lane < nchunks) sums[lane] = x0 - v0;
    if (lane + 32 < nchunks) sums[lane + 32] = x1 - v1;
    if (lane == 0) rowptr[N] = E;
}

__global__ void scan_chunks(const int* __restrict__ deg, const int* __restrict__ csums,
                            int* __restrict__ rowptr, int* __restrict__ cursor, int N) {
    __shared__ int wsum[32];
    int base = blockIdx.x << 10;
    int tid = threadIdx.x, lane = tid & 31, w = tid >> 5;
    int i = base + tid;
    int v = (i < N) ? deg[i] : 0;
    int x = v;
#pragma unroll
    for (int o = 1; o < 32; o <<= 1) {
        int t = __shfl_up_sync(~0u, x, o);
        if (lane >= o) x += t;
    }
    if (lane == 31) wsum[w] = x;
    __syncthreads();
    if (w == 0) {
        int s = wsum[lane];
#pragma unroll
        for (int o = 1; o < 32; o <<= 1) {
            int t = __shfl_up_sync(~0u, s, o);
            if (lane >= o) s += t;
        }
        wsum[lane] = s;
    }
    __syncthreads();
    int excl = x - v + (w ? wsum[w - 1] : 0) + csums[blockIdx.x];
    if (i < N) { rowptr[i] = excl; cursor[i] = excl; }
}

__global__ void fill_csr(const void* __restrict__ ei, int E,
                         const int* __restrict__ flag,
                         int* __restrict__ cursor, int* __restrict__ col) {
    int f64 = flag[0];
    int e = blockIdx.x * blockDim.x + threadIdx.x;
    if (e >= E) return;
    int src = (int)ld_idx(ei, e, f64);
    int dst = (int)ld_idx(ei, (long)E + e, f64);
    int pos = atomicAdd(&cursor[dst], 1);
    col[pos] = src;
}

// ---------------------------------------------------------------------------
// agg[n] = fp16(sum_{j in row n} h[col[j]])  — fp32 accumulation, MLP=2
// 4 nodes per 256-thread block; 64 threads/node, one uint4 (8 halves) each
__global__ void gather_sum(const __half* __restrict__ h, const int* __restrict__ rowptr,
                           const int* __restrict__ col, __half* __restrict__ agg, int N) {
    int node = blockIdx.x * 4 + (threadIdx.x >> 6);
    if (node >= N) return;
    int lane = threadIdx.x & 63;
    int beg = rowptr[node], end = rowptr[node + 1];
    float a[8] = {0.f, 0.f, 0.f, 0.f, 0.f, 0.f, 0.f, 0.f};
    float b[8] = {0.f, 0.f, 0.f, 0.f, 0.f, 0.f, 0.f, 0.f};
    int j = beg;
    for (; j + 2 <= end; j += 2) {
        int s0 = __ldg(col + j);
        int s1 = __ldg(col + j + 1);
        uint4 v0 = ((const uint4*)(h + (size_t)s0 * H))[lane];
        uint4 v1 = ((const uint4*)(h + (size_t)s1 * H))[lane];
        const uint32_t* w0 = &v0.x;
        const uint32_t* w1 = &v1.x;
#pragma unroll
        for (int q = 0; q < 4; q++) {
            float2 p = __half22float2(*(__half2*)&w0[q]);
            float2 r = __half22float2(*(__half2*)&w1[q]);
            a[2 * q] += p.x; a[2 * q + 1] += p.y;
            b[2 * q] += r.x; b[2 * q + 1] += r.y;
        }
    }
    if (j < end) {
        int s0 = __ldg(col + j);
        uint4 v0 = ((const uint4*)(h + (size_t)s0 * H))[lane];
        const uint32_t* w0 = &v0.x;
#pragma unroll
        for (int q = 0; q < 4; q++) {
            float2 p = __half22float2(*(__half2*)&w0[q]);
            a[2 * q] += p.x; a[2 * q + 1] += p.y;
        }
    }
    uint4 o;
    uint32_t* ow = &o.x;
#pragma unroll
    for (int q = 0; q < 4; q++) {
        __half2 r = __floats2half2_rn(a[2 * q] + b[2 * q], a[2 * q + 1] + b[2 * q + 1]);
        ow[q] = *(uint32_t*)&r;
    }
    ((uint4*)(agg + (size_t)node * H))[lane] = o;
}

// ---------------------------------------------------------------------------
// g_Wt[mat][n][k] = fp16(W[mat][k][n])
__global__ void build_wt(const float* __restrict__ Wr, const float* __restrict__ Wn) {
    int mat = blockIdx.z;
    int l = mat >> 1, s = mat & 1;
    const float* W = (s ? Wn : Wr) + (size_t)l * H * H;
    __half* out = g_Wt + (size_t)mat * H * H;
    __shared__ float t[32][33];
    int kx = blockIdx.x * 32, ny = blockIdx.y * 32;
    int tx = threadIdx.x, ty = threadIdx.y;
#pragma unroll
    for (int j = 0; j < 4; j++)
        t[ty + j * 8][tx] = W[(size_t)(kx + ty + j * 8) * H + ny + tx];
    __syncthreads();
#pragma unroll
    for (int j = 0; j < 4; j++)
        out[(size_t)(ny + ty + j * 8) * H + kx + tx] = __float2half_rn(t[tx][ty + j * 8]);
}

// ---------------------------------------------------------------------------
// h0 = fp16(x @ W_in + b_in)
__global__ void in_gemm(const float* __restrict__ x, const float* __restrict__ Win,
                        const float* __restrict__ bin, __half* __restrict__ h, int N) {
    __shared__ float xs[16][17];
    int nb = blockIdx.x * 16;
    int tid = threadIdx.x;
    {
        int n = tid >> 4, k = tid & 15;
        int gn = nb + n;
        xs[n][k] = (gn < N) ? x[(size_t)gn * INF + k] : 0.f;
    }
    __syncthreads();
    float w0[16], w1[16];
#pragma unroll
    for (int k = 0; k < 16; k++) {
        w0[k] = Win[k * H + tid];
        w1[k] = Win[k * H + tid + 256];
    }
    float b0 = bin[tid], b1 = bin[tid + 256];
    for (int n = 0; n < 16; n++) {
        int gn = nb + n;
        if (gn >= N) break;
        float a0 = b0, a1 = b1;
#pragma unroll
        for (int k = 0; k < 16; k++) {
            float xv = xs[n][k];
            a0 += xv * w0[k];
            a1 += xv * w1[k];
        }
        h[(size_t)gn * H + tid]       = __float2half_rn(a0);
        h[(size_t)gn * H + tid + 256] = __float2half_rn(a1);
    }
}

// ---------------------------------------------------------------------------
// C = fp16(A1@W1' + A2@W2' + bias) via fp16 mma.sync m16n8k16 + ldmatrix
//   BM=128, BN=128, BK=32 halves, 8 warps (4x2), warp tile 32x64
//   3-stage cp.async pipeline, 2 CTAs/SM  (R12 proven config)
#define BM 128
#define BN 128
#define BKT 32                                   // halves per K-tile
#define RSW 20                                   // words per row
#define TILE_WORDS (BM * RSW)                    // 2560 words = 10240 B
#define STAGES 3
#define CONV_SMEM (STAGES * 2 * TILE_WORDS * 4)  // 61440 B

__global__ __launch_bounds__(256, 2)
void conv_mma(const __half* __restrict__ A1, const __half* __restrict__ A2,
              const __half* __restrict__ Wt, const float* __restrict__ bias,
              __half* __restrict__ C, int M) {
    extern __shared__ uint32_t smw[];
    uint32_t* Asw = smw;                          // STAGES * TILE_WORDS
    uint32_t* Bsw = smw + STAGES * TILE_WORDS;
    uint32_t aAddr = smem_u32(Asw);
    uint32_t bAddr = smem_u32(Bsw);

    int tid = threadIdx.x;
    int wid = tid >> 5, lane = tid & 31;
    int g = lane >> 2, tig = lane & 3;
    int wm0 = (wid & 3) * 32;
    int wn0 = (wid >> 2) * 64;
    int m0 = blockIdx.x * BM;
    int n0 = blockIdx.y * BN;

    int cprow = tid >> 1;                         // 0..127
    int cpoff = (tid & 1) * 16;                   // halves offset: 0 or 16

    int aRow = lane & 15;
    int aColW = (lane >> 4) << 2;
    int bRow = (lane & 7) + ((lane >> 4) << 3);
    int bColW = ((lane >> 3) & 1) << 2;

    float acc[2][8][4];
#pragma unroll
    for (int i = 0; i < 2; i++)
#pragma unroll
        for (int j = 0; j < 8; j++)
#pragma unroll
            for (int q = 0; q < 4; q++) acc[i][j][q] = 0.f;

    const int NT = 32;                            // 2 sources * 16 K-tiles

    auto issue = [&](int t) {
        int st = t % STAGES;
        int s = t >> 4;
        int kt = (t & 15) * BKT;
        const __half* A = s ? A2 : A1;            // rows < NMAX always valid
        const __half* B = Wt + (size_t)s * H * H;
        uint32_t ab = aAddr + st * (TILE_WORDS * 4);
        uint32_t bb = bAddr + st * (TILE_WORDS * 4);
        uint32_t so = cprow * 80 + cpoff * 2;     // byte offset in tile
        const __half* ag = A + (size_t)(m0 + cprow) * H + kt + cpoff;
        const __half* bg = B + (size_t)(n0 + cprow) * H + kt + cpoff;
        cp_async16(ab + so,      ag);
        cp_async16(ab + so + 16, ag + 8);
        cp_async16(bb + so,      bg);
        cp_async16(bb + so + 16, bg + 8);
        asm volatile("cp.async.commit_group;" ::: "memory");
    };

    issue(0);
    issue(1);

    for (int t = 0; t < NT; t++) {
        if (t + 1 < NT) {
            asm volatile("cp.async.wait_group 1;" ::: "memory");
        } else {
            asm volatile("cp.async.wait_group 0;" ::: "memory");
        }
        __syncthreads();
        if (t + 2 < NT) issue(t + 2);

        uint32_t AsbA = aAddr + (t % STAGES) * (TILE_WORDS * 4);
        uint32_t BsbA = bAddr + (t % STAGES) * (TILE_WORDS * 4);
        uint32_t aBase = AsbA + (wm0 + aRow) * 80 + aColW * 4;
        uint32_t bBase = BsbA + (wn0 + bRow) * 80 + bColW * 4;
#pragma unroll
        for (int ks = 0; ks < 2; ks++) {
            uint32_t ko = ks * 32;                // k16 step = 8 words = 32 B
            uint32_t a[2][4], b[8][2];
#pragma unroll
            for (int i = 0; i < 2; i++)
                ldmatrix_x4(a[i][0], a[i][1], a[i][2], a[i][3],
                            aBase + ko + i * (16 * 80));
#pragma unroll
            for (int jp = 0; jp < 4; jp++)
                ldmatrix_x4(b[2 * jp][0], b[2 * jp][1], b[2 * jp + 1][0], b[2 * jp + 1][1],
                            bBase + ko + jp * (16 * 80));
#pragma unroll
            for (int i = 0; i < 2; i++)
#pragma unroll
                for (int j = 0; j < 8; j++)
                    mma_f16(acc[i][j], a[i], b[j]);
        }
    }

    // epilogue: add bias (fp32), store half2 pairs
#pragma unroll
    for (int i = 0; i < 2; i++) {
        int row0 = m0 + wm0 + i * 16 + g;
        int row1 = row0 + 8;
#pragma unroll
        for (int j = 0; j < 8; j++) {
            int col = n0 + wn0 + j * 8 + tig * 2;
            float bx = bias[col], by = bias[col + 1];
            if (row0 < M) {
                __half2 o = __floats2half2_rn(acc[i][j][0] + bx, acc[i][j][1] + by);
                *(__half2*)(C + (size_t)row0 * H + col) = o;
            }
            if (row1 < M) {
                __half2 o = __floats2half2_rn(acc[i][j][2] + bx, acc[i][j][3] + by);
                *(__half2*)(C + (size_t)row1 * H + col) = o;
            }
        }
    }
}

// ---------------------------------------------------------------------------
// In-place LayerNorm + ReLU; 2 rows per 256-thread block (fp16 storage)
__global__ void ln_relu(__half* __restrict__ h, const float* __restrict__ gamma,
                        const float* __restrict__ beta, int N) {
    long row = blockIdx.x * 2 + (threadIdx.x >> 7);
    if (row >= N) return;
    int tid = threadIdx.x & 127;                  // 128 threads x 4 halves
    int grp = threadIdx.x >> 7;
    uint2 u = ((const uint2*)(h + row * H))[tid];
    float2 p0 = __half22float2(*(__half2*)&u.x);
    float2 p1 = __half22float2(*(__half2*)&u.y);
    float s  = p0.x + p0.y + p1.x + p1.y;
    float sq = p0.x * p0.x + p0.y * p0.y + p1.x * p1.x + p1.y * p1.y;
#pragma unroll
    for (int o = 16; o; o >>= 1) {
        s  += __shfl_xor_sync(~0u, s, o);
        sq += __shfl_xor_sync(~0u, sq, o);
    }
    __shared__ float ss[2][4], sqs[2][4];
    int w = tid >> 5;
    if ((tid & 31) == 0) { ss[grp][w] = s; sqs[grp][w] = sq; }
    __syncthreads();
    s  = ss[grp][0] + ss[grp][1] + ss[grp][2] + ss[grp][3];
    sq = sqs[grp][0] + sqs[grp][1] + sqs[grp][2] + sqs[grp][3];
    float mean = s * (1.f / H);
    float var  = sq * (1.f / H) - mean * mean;
    float rstd = rsqrtf(var + 1e-5f);
    int c = tid * 4;
    float4 gm = *(const float4*)(gamma + c);
    float4 bt = *(const float4*)(beta + c);
    float r0 = fmaxf((p0.x - mean) * rstd * gm.x + bt.x, 0.f);
    float r1 = fmaxf((p0.y - mean) * rstd * gm.y + bt.y, 0.f);
    float r2 = fmaxf((p1.x - mean) * rstd * gm.z + bt.z, 0.f);
    float r3 = fmaxf((p1.y - mean) * rstd * gm.w + bt.w, 0.f);
    __half2 o0 = __floats2half2_rn(r0, r1);
    __half2 o1 = __floats2half2_rn(r2, r3);
    uint2 o; o.x = *(uint32_t*)&o0; o.y = *(uint32_t*)&o1;
    ((uint2*)(h + row * H))[tid] = o;
}

// ---------------------------------------------------------------------------
// pool: 4 nodes per 256-thread block; 64 threads/node, uint4 per thread
__global__ void pool(const __half* __restrict__ h, const void* __restrict__ batch,
                     int N, const int* __restrict__ flag) {
    long n = blockIdx.x * 4 + (threadIdx.x >> 6);
    if (n >= N) return;
    int f64 = flag[0];
    long g = ld_idx(batch, n, f64);
    int lane = threadIdx.x & 63;                  // 64 threads x 8 halves
    uint4 u = ((const uint4*)(h + n * H))[lane];
    const uint32_t* w = &u.x;
    float2 p0 = __half22float2(*(__half2*)&w[0]);
    float2 p1 = __half22float2(*(__half2*)&w[1]);
    float2 p2 = __half22float2(*(__half2*)&w[2]);
    float2 p3 = __half22float2(*(__half2*)&w[3]);
    float* dst = g_pooled + g * H + 8 * lane;
    red_add_v4(dst,     make_float4(p0.x, p0.y, p1.x, p1.y));
    red_add_v4(dst + 4, make_float4(p2.x, p2.y, p3.x, p3.y));
    if (lane == 0) atomicAdd(&g_counts[g], 1.f);
}

__global__ void out_gemm(const float* __restrict__ Wout, const float* __restrict__ bout,
                         float* __restrict__ out) {
    int g = blockIdx.x;
    __shared__ float ps[H];
    int tid = threadIdx.x;
    float inv = 1.f / fmaxf(g_counts[g], 1.f);
#pragma unroll
    for (int i = 0; i < 4; i++)
        ps[tid + i * 128] = g_pooled[(size_t)g * H + tid + i * 128] * inv;
    __syncthreads();
    float acc[4];
#pragma unroll
    for (int j = 0; j < 4; j++) acc[j] = bout[tid + j * 128];
    for (int k = 0; k < H; k++) {
        float p = ps[k];
#pragma unroll
        for (int j = 0; j < 4; j++)
            acc[j] += p * Wout[(size_t)k * H + tid + j * 128];
    }
#pragma unroll
    for (int j = 0; j < 4; j++) out[(size_t)g * H + tid + j * 128] = acc[j];
}

// ---------------------------------------------------------------------------
extern "C" void kernel_launch(void* const* d_in, const int* in_sizes, int n_in,
                              void* d_out, int out_size) {
    const float* x      = (const float*)d_in[0];
    const void*  ei     = d_in[1];
    const void*  batch  = d_in[2];
    const float* W_in   = (const float*)d_in[3];
    const float* b_in   = (const float*)d_in[4];
    const float* W_root = (const float*)d_in[5];
    const float* W_neigh= (const float*)d_in[6];
    const float* b_conv = (const float*)d_in[7];
    const float* ln_g   = (const float*)d_in[8];
    const float* ln_b   = (const float*)d_in[9];
    const float* W_out  = (const float*)d_in[10];
    const float* b_out  = (const float*)d_in[11];
    float* out = (float*)d_out;

    int N = in_sizes[0] / INF;
    int E = in_sizes[1] / 2;
    int G = out_size / H;
    int nchunks = (N + 1023) / 1024;

    void *pA, *pB, *pAgg, *pWt, *pPool, *pCnt, *pFlags;
    void *pDeg, *pRow, *pCur, *pCsums, *pCol;
    cudaGetSymbolAddress(&pA, g_hA);
    cudaGetSymbolAddress(&pB, g_hB);
    cudaGetSymbolAddress(&pAgg, g_agg);
    cudaGetSymbolAddress(&pWt, g_Wt);
    cudaGetSymbolAddress(&pPool, g_pooled);
    cudaGetSymbolAddress(&pCnt, g_counts);
    cudaGetSymbolAddress(&pFlags, g_flags);
    cudaGetSymbolAddress(&pDeg, g_deg);
    cudaGetSymbolAddress(&pRow, g_rowptr);
    cudaGetSymbolAddress(&pCur, g_cursor);
    cudaGetSymbolAddress(&pCsums, g_csums);
    cudaGetSymbolAddress(&pCol, g_col);
    __half* hA = (__half*)pA;
    __half* hB = (__half*)pB;
    int* flags = (int*)pFlags;

    cudaFuncSetAttribute(conv_mma, cudaFuncAttributeMaxDynamicSharedMemorySize, CONV_SMEM);

    cudaMemsetAsync(pFlags, 1, 2 * sizeof(int));
    {
        long nw = in_sizes[1];
        int blocks = (int)((nw / 2 + 255) / 256);
        detect_i64<<<blocks, 256>>>((const int*)ei, nw, flags + 0);
        nw = in_sizes[2];
        blocks = (int)((nw / 2 + 255) / 256);
        detect_i64<<<blocks, 256>>>((const int*)batch, nw, flags + 1);
    }

    // CSR build (once per call; graph identical across layers)
    cudaMemsetAsync(pDeg, 0, (size_t)N * sizeof(int));
    hist_dst<<<(E + 255) / 256, 256>>>(ei, E, flags, (int*)pDeg);
    chunk_sums<<<nchunks, 256>>>((const int*)pDeg, (int*)pCsums, N);
    scan_sums<<<1, 32>>>((int*)pCsums, (int*)pRow, nchunks, N, E);
    scan_chunks<<<nchunks, 1024>>>((const int*)pDeg, (const int*)pCsums,
                                   (int*)pRow, (int*)pCur, N);
    fill_csr<<<(E + 255) / 256, 256>>>(ei, E, flags, (int*)pCur, (int*)pCol);

    {
        dim3 g2(16, 16, 6);
        build_wt<<<g2, dim3(32, 8)>>>(W_root, W_neigh);
    }
    in_gemm<<<(N + 15) / 16, 256>>>(x, W_in, b_in, hA, N);

    __half* cur = hA;
    __half* nxt = hB;
    for (int l = 0; l < LAYERS; l++) {
        gather_sum<<<(N + 3) / 4, 256>>>(cur, (const int*)pRow, (const int*)pCol,
                                         (__half*)pAgg, N);
        dim3 grid((N + BM - 1) / BM, H / BN);
        conv_mma<<<grid, 256, CONV_SMEM>>>(cur, (const __half*)pAgg,
                                           (const __half*)pWt + (size_t)l * 2 * H * H,
                                           b_conv + (size_t)l * H, nxt, N);
        ln_relu<<<(N + 1) / 2, 256>>>(nxt, ln_g + (size_t)l * H, ln_b + (size_t)l * H, N);
        __half* t = cur; cur = nxt; nxt = t;
    }

    cudaMemsetAsync(pPool, 0, (size_t)G * H * sizeof(float));
    cudaMemsetAsync(pCnt, 0, G * sizeof(float));
    pool<<<(N + 3) / 4, 256>>>(cur, batch, N, flags + 1);
    out_gemm<<<G, 128>>>(W_out, b_out, out);
}

// round 17
// speedup vs baseline: 1.0793x; 1.0246x over previous
#include <cuda_runtime.h>
#include <cuda_fp16.h>
#include <cstdint>

// ---------------------------------------------------------------------------
// FragmentGraphEncoder: GNN forward  (R12 kernels, stream-forked preamble)
//   fp16 mma.sync (m16n8k16) conv GEMMs, BM=128 BN=128, 256 thr, ldmatrix
//   fragment loads, cp.async 3-stage pipeline (2 CTAs/SM), CSR aggregation
// ---------------------------------------------------------------------------

#define H 512
#define INF 16
#define LAYERS 3
#define NMAX 50176
#define GMAX 512
#define EMAX 1048576

__device__ __half g_hA[(size_t)NMAX * H];
__device__ __half g_hB[(size_t)NMAX * H];
__device__ __half g_agg[(size_t)NMAX * H];
__device__ __half g_Wt[(size_t)LAYERS * 2 * H * H];   // fp16, [n][k]
__device__ float  g_pooled[GMAX * H];
__device__ float  g_counts[GMAX];
__device__ int    g_flags[2];
// CSR scratch
__device__ int    g_deg[NMAX];
__device__ int    g_rowptr[NMAX + 1];
__device__ int    g_cursor[NMAX];
__device__ int    g_csums[64];
__device__ int    g_col[EMAX];

// ---------------------------------------------------------------------------
__device__ __forceinline__ void red_add_v4(float* addr, float4 v) {
    asm volatile("red.global.add.v4.f32 [%0], {%1, %2, %3, %4};"
                 :: "l"(addr), "f"(v.x), "f"(v.y), "f"(v.z), "f"(v.w) : "memory");
}
__device__ __forceinline__ void mma_f16(float* c, const uint32_t* a, const uint32_t* b) {
    asm("mma.sync.aligned.m16n8k16.row.col.f32.f16.f16.f32 "
        "{%0,%1,%2,%3}, {%4,%5,%6,%7}, {%8,%9}, {%0,%1,%2,%3};"
        : "+f"(c[0]), "+f"(c[1]), "+f"(c[2]), "+f"(c[3])
        : "r"(a[0]), "r"(a[1]), "r"(a[2]), "r"(a[3]), "r"(b[0]), "r"(b[1]));
}
__device__ __forceinline__ void ldmatrix_x4(uint32_t& r0, uint32_t& r1,
                                            uint32_t& r2, uint32_t& r3, uint32_t addr) {
    asm volatile("ldmatrix.sync.aligned.m8n8.x4.shared.b16 {%0,%1,%2,%3}, [%4];"
                 : "=r"(r0), "=r"(r1), "=r"(r2), "=r"(r3) : "r"(addr));
}
__device__ __forceinline__ uint32_t smem_u32(const void* p) {
    uint32_t a;
    asm("{ .reg .u64 t; cvta.to.shared.u64 t, %1; cvt.u32.u64 %0, t; }" : "=r"(a) : "l"(p));
    return a;
}
__device__ __forceinline__ void cp_async16(uint32_t dst, const void* src) {
    asm volatile("cp.async.cg.shared.global [%0], [%1], 16;" :: "r"(dst), "l"(src));
}

// Detect int64 vs int32 index buffers
__global__ void detect_i64(const int* __restrict__ w, long n_words, int* flag) {
    long i = (long)blockIdx.x * blockDim.x + threadIdx.x;
    long idx = 2 * i + 1;
    if (idx < n_words && w[idx] != 0) *flag = 0;
}
__device__ __forceinline__ long ld_idx(const void* p, long i, int f64) {
    return f64 ? (long)((const long long*)p)[i] : (long)((const int*)p)[i];
}

// ---------------------------------------------------------------------------
// CSR build (graph is layer-invariant: build once per call)
__global__ void hist_dst(const void* __restrict__ ei, int E,
                         const int* __restrict__ flag, int* __restrict__ deg) {
    int f64 = flag[0];
    int e = blockIdx.x * blockDim.x + threadIdx.x;
    if (e >= E) return;
    int dst = (int)ld_idx(ei, (long)E + e, f64);
    atomicAdd(&deg[dst], 1);
}

__global__ void chunk_sums(const int* __restrict__ deg, int* __restrict__ sums, int N) {
    __shared__ int ws[8];
    int base = blockIdx.x << 10;
    int tid = threadIdx.x;            // 256
    int v = 0;
#pragma unroll
    for (int i = 0; i < 4; i++) {
        int idx = base + tid + i * 256;
        v += (idx < N) ? deg[idx] : 0;
    }
#pragma unroll
    for (int o = 16; o; o >>= 1) v += __shfl_xor_sync(~0u, v, o);
    if ((tid & 31) == 0) ws[tid >> 5] = v;
    __syncthreads();
    if (tid == 0) {
        int s = 0;
#pragma unroll
        for (int i = 0; i < 8; i++) s += ws[i];
        sums[blockIdx.x] = s;
    }
}

__global__ void scan_sums(int* __restrict__ sums, int* __restrict__ rowptr,
                          int nchunks, int N, int E) {
    int lane = threadIdx.x;
    int v0 = (lane < nchunks) ? sums[lane] : 0;
    int v1 = (lane + 32 < nchunks) ? sums[lane + 32] : 0;
    int x0 = v0;
#pragma unroll
    for (int o = 1; o < 32; o <<= 1) {
        int t = __shfl_up_sync(~0u, x0, o);
        if (lane >= o) x0 += t;
    }
    int tot0 = __shfl_sync(~0u, x0, 31);
    int x1 = v1;
#pragma unroll
    for (int o = 1; o < 32; o <<= 1) {
        int t = __shfl_up_sync(~0u, x1, o);
        if (lane >= o) x1 += t;
    }
    x1 += tot0;
    if (lane < nchunks) sums[lane] = x0 - v0;
    if (lane + 32 < nchunks) sums[lane + 32] = x1 - v1;
    if (lane == 0) rowptr[N] = E;
}

__global__ void scan_chunks(const int* __restrict__ deg, const int* __restrict__ csums,
                            int* __restrict__ rowptr, int* __restrict__ cursor, int N) {
    __shared__ int wsum[32];
    int base = blockIdx.x << 10;
    int tid = threadIdx.x, lane = tid & 31, w = tid >> 5;
    int i = base + tid;
    int v = (i < N) ? deg[i] : 0;
    int x = v;
#pragma unroll
    for (int o = 1; o < 32; o <<= 1) {
        int t = __shfl_up_sync(~0u, x, o);
        if (lane >= o) x += t;
    }
    if (lane == 31) wsum[w] = x;
    __syncthreads();
    if (w == 0) {
        int s = wsum[lane];
#pragma unroll
        for (int o = 1; o < 32; o <<= 1) {
            int t = __shfl_up_sync(~0u, s, o);
            if (lane >= o) s += t;
        }
        wsum[lane] = s;
    }
    __syncthreads();
    int excl = x - v + (w ? wsum[w - 1] : 0) + csums[blockIdx.x];
    if (i < N) { rowptr[i] = excl; cursor[i] = excl; }
}

__global__ void fill_csr(const void* __restrict__ ei, int E,
                         const int* __restrict__ flag,
                         int* __restrict__ cursor, int* __restrict__ col) {
    int f64 = flag[0];
    int e = blockIdx.x * blockDim.x + threadIdx.x;
    if (e >= E) return;
    int src = (int)ld_idx(ei, e, f64);
    int dst = (int)ld_idx(ei, (long)E + e, f64);
    int pos = atomicAdd(&cursor[dst], 1);
    col[pos] = src;
}

// ---------------------------------------------------------------------------
// agg[n] = fp16(sum_{j in row n} h[col[j]])  — fp32 accumulation, MLP=2
// 4 nodes per 256-thread block; 64 threads/node, one uint4 (8 halves) each
__global__ void gather_sum(const __half* __restrict__ h, const int* __restrict__ rowptr,
                           const int* __restrict__ col, __half* __restrict__ agg, int N) {
    int node = blockIdx.x * 4 + (threadIdx.x >> 6);
    if (node >= N) return;
    int lane = threadIdx.x & 63;
    int beg = rowptr[node], end = rowptr[node + 1];
    float a[8] = {0.f, 0.f, 0.f, 0.f, 0.f, 0.f, 0.f, 0.f};
    float b[8] = {0.f, 0.f, 0.f, 0.f, 0.f, 0.f, 0.f, 0.f};
    int j = beg;
    for (; j + 2 <= end; j += 2) {
        int s0 = __ldg(col + j);
        int s1 = __ldg(col + j + 1);
        uint4 v0 = ((const uint4*)(h + (size_t)s0 * H))[lane];
        uint4 v1 = ((const uint4*)(h + (size_t)s1 * H))[lane];
        const uint32_t* w0 = &v0.x;
        const uint32_t* w1 = &v1.x;
#pragma unroll
        for (int q = 0; q < 4; q++) {
            float2 p = __half22float2(*(__half2*)&w0[q]);
            float2 r = __half22float2(*(__half2*)&w1[q]);
            a[2 * q] += p.x; a[2 * q + 1] += p.y;
            b[2 * q] += r.x; b[2 * q + 1] += r.y;
        }
    }
    if (j < end) {
        int s0 = __ldg(col + j);
        uint4 v0 = ((const uint4*)(h + (size_t)s0 * H))[lane];
        const uint32_t* w0 = &v0.x;
#pragma unroll
        for (int q = 0; q < 4; q++) {
            float2 p = __half22float2(*(__half2*)&w0[q]);
            a[2 * q] += p.x; a[2 * q + 1] += p.y;
        }
    }
    uint4 o;
    uint32_t* ow = &o.x;
#pragma unroll
    for (int q = 0; q < 4; q++) {
        __half2 r = __floats2half2_rn(a[2 * q] + b[2 * q], a[2 * q + 1] + b[2 * q + 1]);
        ow[q] = *(uint32_t*)&r;
    }
    ((uint4*)(agg + (size_t)node * H))[lane] = o;
}

// ---------------------------------------------------------------------------
// g_Wt[mat][n][k] = fp16(W[mat][k][n])
__global__ void build_wt(const float* __restrict__ Wr, const float* __restrict__ Wn) {
    int mat = blockIdx.z;
    int l = mat >> 1, s = mat & 1;
    const float* W = (s ? Wn : Wr) + (size_t)l * H * H;
    __half* out = g_Wt + (size_t)mat * H * H;
    __shared__ float t[32][33];
    int kx = blockIdx.x * 32, ny = blockIdx.y * 32;
    int tx = threadIdx.x, ty = threadIdx.y;
#pragma unroll
    for (int j = 0; j < 4; j++)
        t[ty + j * 8][tx] = W[(size_t)(kx + ty + j * 8) * H + ny + tx];
    __syncthreads();
#pragma unroll
    for (int j = 0; j < 4; j++)
        out[(size_t)(ny + ty + j * 8) * H + kx + tx] = __float2half_rn(t[tx][ty + j * 8]);
}

// ---------------------------------------------------------------------------
// h0 = fp16(x @ W_in + b_in)
__global__ void in_gemm(const float* __restrict__ x, const float* __restrict__ Win,
                        const float* __restrict__ bin, __half* __restrict__ h, int N) {
    __shared__ float xs[16][17];
    int nb = blockIdx.x * 16;
    int tid = threadIdx.x;
    {
        int n = tid >> 4, k = tid & 15;
        int gn = nb + n;
        xs[n][k] = (gn < N) ? x[(size_t)gn * INF + k] : 0.f;
    }
    __syncthreads();
    float w0[16], w1[16];
#pragma unroll
    for (int k = 0; k < 16; k++) {
        w0[k] = Win[k * H + tid];
        w1[k] = Win[k * H + tid + 256];
    }
    float b0 = bin[tid], b1 = bin[tid + 256];
    for (int n = 0; n < 16; n++) {
        int gn = nb + n;
        if (gn >= N) break;
        float a0 = b0, a1 = b1;
#pragma unroll
        for (int k = 0; k < 16; k++) {
            float xv = xs[n][k];
            a0 += xv * w0[k];
            a1 += xv * w1[k];
        }
        h[(size_t)gn * H + tid]       = __float2half_rn(a0);
        h[(size_t)gn * H + tid + 256] = __float2half_rn(a1);
    }
}

// ---------------------------------------------------------------------------
// C = fp16(A1@W1' + A2@W2' + bias) via fp16 mma.sync m16n8k16 + ldmatrix
//   BM=128, BN=128, BK=32 halves, 8 warps (4x2), warp tile 32x64
//   3-stage cp.async pipeline, 2 CTAs/SM  (R12 proven config)
#define BM 128
#define BN 128
#define BKT 32                                   // halves per K-tile
#define RSW 20                                   // words per row
#define TILE_WORDS (BM * RSW)                    // 2560 words = 10240 B
#define STAGES 3
#define CONV_SMEM (STAGES * 2 * TILE_WORDS * 4)  // 61440 B

__global__ __launch_bounds__(256, 2)
void conv_mma(const __half* __restrict__ A1, const __half* __restrict__ A2,
              const __half* __restrict__ Wt, const float* __restrict__ bias,
              __half* __restrict__ C, int M) {
    extern __shared__ uint32_t smw[];
    uint32_t* Asw = smw;                          // STAGES * TILE_WORDS
    uint32_t* Bsw = smw + STAGES * TILE_WORDS;
    uint32_t aAddr = smem_u32(Asw);
    uint32_t bAddr = smem_u32(Bsw);

    int tid = threadIdx.x;
    int wid = tid >> 5, lane = tid & 31;
    int g = lane >> 2, tig = lane & 3;
    int wm0 = (wid & 3) * 32;
    int wn0 = (wid >> 2) * 64;
    int m0 = blockIdx.x * BM;
    int n0 = blockIdx.y * BN;

    int cprow = tid >> 1;                         // 0..127
    int cpoff = (tid & 1) * 16;                   // halves offset: 0 or 16

    int aRow = lane & 15;
    int aColW = (lane >> 4) << 2;
    int bRow = (lane & 7) + ((lane >> 4) << 3);
    int bColW = ((lane >> 3) & 1) << 2;

    float acc[2][8][4];
#pragma unroll
    for (int i = 0; i < 2; i++)
#pragma unroll
        for (int j = 0; j < 8; j++)
#pragma unroll
            for (int q = 0; q < 4; q++) acc[i][j][q] = 0.f;

    const int NT = 32;                            // 2 sources * 16 K-tiles

    auto issue = [&](int t) {
        int st = t % STAGES;
        int s = t >> 4;
        int kt = (t & 15) * BKT;
        const __half* A = s ? A2 : A1;            // rows < NMAX always valid
        const __half* B = Wt + (size_t)s * H * H;
        uint32_t ab = aAddr + st * (TILE_WORDS * 4);
        uint32_t bb = bAddr + st * (TILE_WORDS * 4);
        uint32_t so = cprow * 80 + cpoff * 2;     // byte offset in tile
        const __half* ag = A + (size_t)(m0 + cprow) * H + kt + cpoff;
        const __half* bg = B + (size_t)(n0 + cprow) * H + kt + cpoff;
        cp_async16(ab + so,      ag);
        cp_async16(ab + so + 16, ag + 8);
        cp_async16(bb + so,      bg);
        cp_async16(bb + so + 16, bg + 8);
        asm volatile("cp.async.commit_group;" ::: "memory");
    };

    issue(0);
    issue(1);

    for (int t = 0; t < NT; t++) {
        if (t + 1 < NT) {
            asm volatile("cp.async.wait_group 1;" ::: "memory");
        } else {
            asm volatile("cp.async.wait_group 0;" ::: "memory");
        }
        __syncthreads();
        if (t + 2 < NT) issue(t + 2);

        uint32_t AsbA = aAddr + (t % STAGES) * (TILE_WORDS * 4);
        uint32_t BsbA = bAddr + (t % STAGES) * (TILE_WORDS * 4);
        uint32_t aBase = AsbA + (wm0 + aRow) * 80 + aColW * 4;
        uint32_t bBase = BsbA + (wn0 + bRow) * 80 + bColW * 4;
#pragma unroll
        for (int ks = 0; ks < 2; ks++) {
            uint32_t ko = ks * 32;                // k16 step = 8 words = 32 B
            uint32_t a[2][4], b[8][2];
#pragma unroll
            for (int i = 0; i < 2; i++)
                ldmatrix_x4(a[i][0], a[i][1], a[i][2], a[i][3],
                            aBase + ko + i * (16 * 80));
#pragma unroll
            for (int jp = 0; jp < 4; jp++)
                ldmatrix_x4(b[2 * jp][0], b[2 * jp][1], b[2 * jp + 1][0], b[2 * jp + 1][1],
                            bBase + ko + jp * (16 * 80));
#pragma unroll
            for (int i = 0; i < 2; i++)
#pragma unroll
                for (int j = 0; j < 8; j++)
                    mma_f16(acc[i][j], a[i], b[j]);
        }
    }

    // epilogue: add bias (fp32), store half2 pairs
#pragma unroll
    for (int i = 0; i < 2; i++) {
        int row0 = m0 + wm0 + i * 16 + g;
        int row1 = row0 + 8;
#pragma unroll
        for (int j = 0; j < 8; j++) {
            int col = n0 + wn0 + j * 8 + tig * 2;
            float bx = bias[col], by = bias[col + 1];
            if (row0 < M) {
                __half2 o = __floats2half2_rn(acc[i][j][0] + bx, acc[i][j][1] + by);
                *(__half2*)(C + (size_t)row0 * H + col) = o;
            }
            if (row1 < M) {
                __half2 o = __floats2half2_rn(acc[i][j][2] + bx, acc[i][j][3] + by);
                *(__half2*)(C + (size_t)row1 * H + col) = o;
            }
        }
    }
}

// ---------------------------------------------------------------------------
// In-place LayerNorm + ReLU per row (fp16 storage, fp32 math)  [R12 config]
__global__ void ln_relu(__half* __restrict__ h, const float* __restrict__ gamma,
                        const float* __restrict__ beta, int N) {
    long row = blockIdx.x;
    if (row >= N) return;
    int tid = threadIdx.x;                        // 128 threads x 4 halves
    uint2 u = ((const uint2*)(h + row * H))[tid];
    float2 p0 = __half22float2(*(__half2*)&u.x);
    float2 p1 = __half22float2(*(__half2*)&u.y);
    float s  = p0.x + p0.y + p1.x + p1.y;
    float sq = p0.x * p0.x + p0.y * p0.y + p1.x * p1.x + p1.y * p1.y;
#pragma unroll
    for (int o = 16; o; o >>= 1) {
        s  += __shfl_xor_sync(~0u, s, o);
        sq += __shfl_xor_sync(~0u, sq, o);
    }
    __shared__ float ss[4], sqs[4];
    int w = tid >> 5;
    if ((tid & 31) == 0) { ss[w] = s; sqs[w] = sq; }
    __syncthreads();
    s  = ss[0] + ss[1] + ss[2] + ss[3];
    sq = sqs[0] + sqs[1] + sqs[2] + sqs[3];
    float mean = s * (1.f / H);
    float var  = sq * (1.f / H) - mean * mean;
    float rstd = rsqrtf(var + 1e-5f);
    int c = tid * 4;
    float4 gm = *(const float4*)(gamma + c);
    float4 bt = *(const float4*)(beta + c);
    float r0 = fmaxf((p0.x - mean) * rstd * gm.x + bt.x, 0.f);
    float r1 = fmaxf((p0.y - mean) * rstd * gm.y + bt.y, 0.f);
    float r2 = fmaxf((p1.x - mean) * rstd * gm.z + bt.z, 0.f);
    float r3 = fmaxf((p1.y - mean) * rstd * gm.w + bt.w, 0.f);
    __half2 o0 = __floats2half2_rn(r0, r1);
    __half2 o1 = __floats2half2_rn(r2, r3);
    uint2 o; o.x = *(uint32_t*)&o0; o.y = *(uint32_t*)&o1;
    ((uint2*)(h + row * H))[tid] = o;
}

// ---------------------------------------------------------------------------
// pool per node, 128 threads x uint2  [R12 config]
__global__ void pool(const __half* __restrict__ h, const void* __restrict__ batch,
                     int N, const int* __restrict__ flag) {
    long n = blockIdx.x;
    if (n >= N) return;
    int f64 = flag[0];
    long g = ld_idx(batch, n, f64);
    int lane = threadIdx.x;                       // 128 threads x 4 halves
    uint2 u = ((const uint2*)(h + n * H))[lane];
    float2 p0 = __half22float2(*(__half2*)&u.x);
    float2 p1 = __half22float2(*(__half2*)&u.y);
    red_add_v4(g_pooled + g * H + 4 * lane, make_float4(p0.x, p0.y, p1.x, p1.y));
    if (lane == 0) atomicAdd(&g_counts[g], 1.f);
}

__global__ void out_gemm(const float* __restrict__ Wout, const float* __restrict__ bout,
                         float* __restrict__ out) {
    int g = blockIdx.x;
    __shared__ float ps[H];
    int tid = threadIdx.x;
    float inv = 1.f / fmaxf(g_counts[g], 1.f);
#pragma unroll
    for (int i = 0; i < 4; i++)
        ps[tid + i * 128] = g_pooled[(size_t)g * H + tid + i * 128] * inv;
    __syncthreads();
    float acc[4];
#pragma unroll
    for (int j = 0; j < 4; j++) acc[j] = bout[tid + j * 128];
    for (int k = 0; k < H; k++) {
        float p = ps[k];
#pragma unroll
        for (int j = 0; j < 4; j++)
            acc[j] += p * Wout[(size_t)k * H + tid + j * 128];
    }
#pragma unroll
    for (int j = 0; j < 4; j++) out[(size_t)g * H + tid + j * 128] = acc[j];
}

// ---------------------------------------------------------------------------
extern "C" void kernel_launch(void* const* d_in, const int* in_sizes, int n_in,
                              void* d_out, int out_size) {
    const float* x      = (const float*)d_in[0];
    const void*  ei     = d_in[1];
    const void*  batch  = d_in[2];
    const float* W_in   = (const float*)d_in[3];
    const float* b_in   = (const float*)d_in[4];
    const float* W_root = (const float*)d_in[5];
    const float* W_neigh= (const float*)d_in[6];
    const float* b_conv = (const float*)d_in[7];
    const float* ln_g   = (const float*)d_in[8];
    const float* ln_b   = (const float*)d_in[9];
    const float* W_out  = (const float*)d_in[10];
    const float* b_out  = (const float*)d_in[11];
    float* out = (float*)d_out;

    int N = in_sizes[0] / INF;
    int E = in_sizes[1] / 2;
    int G = out_size / H;
    int nchunks = (N + 1023) / 1024;

    void *pA, *pB, *pAgg, *pWt, *pPool, *pCnt, *pFlags;
    void *pDeg, *pRow, *pCur, *pCsums, *pCol;
    cudaGetSymbolAddress(&pA, g_hA);
    cudaGetSymbolAddress(&pB, g_hB);
    cudaGetSymbolAddress(&pAgg, g_agg);
    cudaGetSymbolAddress(&pWt, g_Wt);
    cudaGetSymbolAddress(&pPool, g_pooled);
    cudaGetSymbolAddress(&pCnt, g_counts);
    cudaGetSymbolAddress(&pFlags, g_flags);
    cudaGetSymbolAddress(&pDeg, g_deg);
    cudaGetSymbolAddress(&pRow, g_rowptr);
    cudaGetSymbolAddress(&pCur, g_cursor);
    cudaGetSymbolAddress(&pCsums, g_csums);
    cudaGetSymbolAddress(&pCol, g_col);
    __half* hA = (__half*)pA;
    __half* hB = (__half*)pB;
    int* flags = (int*)pFlags;

    // one-time resources (created on the uncaptured correctness call)
    static cudaStream_t s2 = nullptr;
    static cudaEvent_t evFork = nullptr, evJoin = nullptr;
    if (s2 == nullptr) {
        cudaStreamCreateWithFlags(&s2, cudaStreamNonBlocking);
        cudaEventCreateWithFlags(&evFork, cudaEventDisableTiming);
        cudaEventCreateWithFlags(&evJoin, cudaEventDisableTiming);
        cudaFuncSetAttribute(conv_mma, cudaFuncAttributeMaxDynamicSharedMemorySize,
                             CONV_SMEM);
    }

    cudaMemsetAsync(pFlags, 1, 2 * sizeof(int));
    {
        long nw = in_sizes[1];
        int blocks = (int)((nw / 2 + 255) / 256);
        detect_i64<<<blocks, 256>>>((const int*)ei, nw, flags + 0);
        nw = in_sizes[2];
        blocks = (int)((nw / 2 + 255) / 256);
        detect_i64<<<blocks, 256>>>((const int*)batch, nw, flags + 1);
    }

    // fork: CSR build on s2, weights + h0 on the main stream
    cudaEventRecord(evFork, 0);
    cudaStreamWaitEvent(s2, evFork, 0);

    cudaMemsetAsync(pDeg, 0, (size_t)N * sizeof(int), s2);
    hist_dst<<<(E + 255) / 256, 256, 0, s2>>>(ei, E, flags, (int*)pDeg);
    chunk_sums<<<nchunks, 256, 0, s2>>>((const int*)pDeg, (int*)pCsums, N);
    scan_sums<<<1, 32, 0, s2>>>((int*)pCsums, (int*)pRow, nchunks, N, E);
    scan_chunks<<<nchunks, 1024, 0, s2>>>((const int*)pDeg, (const int*)pCsums,
                                          (int*)pRow, (int*)pCur, N);
    fill_csr<<<(E + 255) / 256, 256, 0, s2>>>(ei, E, flags, (int*)pCur, (int*)pCol);
    cudaEventRecord(evJoin, s2);

    cudaMemsetAsync(pPool, 0, (size_t)G * H * sizeof(float));
    cudaMemsetAsync(pCnt, 0, G * sizeof(float));
    {
        dim3 g2(16, 16, 6);
        build_wt<<<g2, dim3(32, 8)>>>(W_root, W_neigh);
    }
    in_gemm<<<(N + 15) / 16, 256>>>(x, W_in, b_in, hA, N);

    // join before the first gather needs the CSR
    cudaStreamWaitEvent(0, evJoin, 0);

    __half* cur = hA;
    __half* nxt = hB;
    for (int l = 0; l < LAYERS; l++) {
        gather_sum<<<(N + 3) / 4, 256>>>(cur, (const int*)pRow, (const int*)pCol,
                                         (__half*)pAgg, N);
        dim3 grid((N + BM - 1) / BM, H / BN);
        conv_mma<<<grid, 256, CONV_SMEM>>>(cur, (const __half*)pAgg,
                                           (const __half*)pWt + (size_t)l * 2 * H * H,
                                           b_conv + (size_t)l * H, nxt, N);
        ln_relu<<<N, 128>>>(nxt, ln_g + (size_t)l * H, ln_b + (size_t)l * H, N);
        __half* t = cur; cur = nxt; nxt = t;
    }

    pool<<<N, 128>>>(cur, batch, N, flags + 1);
    out_gemm<<<G, 128>>>(W_out, b_out, out);
}